// round 1
// baseline (speedup 1.0000x reference)
#include <cuda_runtime.h>
#include <math.h>
#include <stdint.h>

#define NN 40000
#define NR 474
#define E1 100000
#define NHOP 30000
#define ET 130000
#define D1 100
#define D2 200
#define NB 8192
#define EPSV 1e-12f

// ---------------- device scratch (no allocation allowed) ----------------
__device__ float g_ent[NN * D1];          // l2-normalized entity embeddings
__device__ float g_Y1[NN * 400];          // [n][h*200 + ts*100 + j]  layer-1 projections
__device__ float g_Y2[NN * 400];          // [n][ts*200 + j]          layer-2 projections
__device__ float g_x[NN * D2];            // layer-1 output (concat heads, elu)
__device__ float g_h2[NN * D2];           // layer-2 output
__device__ float g_pre[NN * D2];          // ent @ W_entities
__device__ float g_p1[NN * 4];            // node scalars: (t0,s0,t1,s1)
__device__ float g_p2[NN * 2];            // node scalars layer2: (t,s)
__device__ float g_mask[NN];
__device__ int   g_tgt[ET], g_src[ET], g_relA[ET], g_relB[ET];
__device__ float g_ee1[ET * 2];
__device__ float g_ee2[ET];
__device__ int   g_cnt[NN];
__device__ int   g_rowptr[NN + 1];
__device__ int   g_fill[NN];
__device__ int   g_csr[ET];
__device__ float g_B1[D1 * 400];
__device__ float g_B2[D2 * 400];
__device__ float g_w1[2 * NR * D1];       // rel projections layer1 per head
__device__ float g_w2[NR * D2];           // rel projections layer2
__device__ float g_q1[2 * NR];            // rel scalars layer1
__device__ float g_q2[NR];                // rel scalars layer2
__device__ float g_u1[4 * D1];            // a_t.T@a2 / a_s.T@a2 per head
__device__ float g_u2[2 * D2];
__device__ float g_or1[NR * D2];          // out_relation_1

// ---------------- init / graph build ----------------
__global__ void k_init() {
    int i = blockIdx.x * blockDim.x + threadIdx.x;
    if (i < NN) { g_cnt[i] = 0; g_mask[i] = 0.f; }
}

__global__ void k_build_edges(const int* __restrict__ edge_list,
                              const int* __restrict__ edge_type,
                              const int* __restrict__ nhop) {
    int e = blockIdx.x * blockDim.x + threadIdx.x;
    if (e >= ET) return;
    int t, s, ra, rb;
    if (e < E1) {
        t = edge_list[e]; s = edge_list[E1 + e];
        ra = edge_type[e]; rb = -1;
    } else {
        int i = e - E1;
        t = nhop[i * 4 + 3]; s = nhop[i * 4 + 0];
        ra = nhop[i * 4 + 1]; rb = nhop[i * 4 + 2];
    }
    g_tgt[e] = t; g_src[e] = s; g_relA[e] = ra; g_relB[e] = rb;
    atomicAdd(&g_cnt[t], 1);
}

__global__ void k_scan() {
    __shared__ int sh[1024];
    int t = threadIdx.x;
    int running = 0;
    for (int base = 0; base < NN; base += 1024) {
        int idx = base + t;
        int v = (idx < NN) ? g_cnt[idx] : 0;
        sh[t] = v;
        __syncthreads();
        for (int off = 1; off < 1024; off <<= 1) {
            int add = (t >= off) ? sh[t - off] : 0;
            __syncthreads();
            sh[t] += add;
            __syncthreads();
        }
        int incl = sh[t];
        if (idx < NN) {
            int excl = running + incl - v;
            g_rowptr[idx] = excl;
            g_fill[idx] = excl;
        }
        int total = sh[1023];
        __syncthreads();
        running += total;
    }
    if (t == 0) g_rowptr[NN] = running;
}

__global__ void k_fill() {
    int e = blockIdx.x * blockDim.x + threadIdx.x;
    if (e >= ET) return;
    int t = g_tgt[e];
    int pos = atomicAdd(&g_fill[t], 1);
    g_csr[pos] = e;
}

__global__ void k_mask_set(const int* __restrict__ batch_inputs) {
    int i = blockIdx.x * blockDim.x + threadIdx.x;
    if (i < NB) g_mask[batch_inputs[i * 3 + 2]] = 1.0f;
}

// ---------------- small prep kernels ----------------
__global__ void k_norm_ent(const float* __restrict__ emb) {
    int w = (blockIdx.x * blockDim.x + threadIdx.x) >> 5;
    int lane = threadIdx.x & 31;
    if (w >= NN) return;
    float v[4]; float ss = 0.f;
#pragma unroll
    for (int j = 0; j < 4; j++) {
        int d = lane + 32 * j;
        v[j] = (d < D1) ? emb[w * D1 + d] : 0.f;
        ss += v[j] * v[j];
    }
#pragma unroll
    for (int o = 16; o; o >>= 1) ss += __shfl_xor_sync(0xffffffffu, ss, o);
    float inv = 1.f / fmaxf(sqrtf(ss), EPSV);
#pragma unroll
    for (int j = 0; j < 4; j++) {
        int d = lane + 32 * j;
        if (d < D1) g_ent[w * D1 + d] = v[j] * inv;
    }
}

__global__ void k_or1(const float* __restrict__ rel_emb,
                      const float* __restrict__ W_rel,
                      float* __restrict__ out) {
    int i = blockIdx.x * blockDim.x + threadIdx.x;
    if (i >= NR * D2) return;
    int r = i / D2, d = i % D2;
    float s = 0.f;
#pragma unroll 4
    for (int k = 0; k < D1; k++) s += rel_emb[r * D1 + k] * W_rel[k * D2 + d];
    g_or1[i] = s;
    out[NN * D2 + i] = s;
}

__global__ void k_B1(const float* __restrict__ att_a) {
    int i = blockIdx.x * blockDim.x + threadIdx.x;
    if (i >= D1 * 400) return;
    int k = i / 400, c = i % 400;
    int h = c / 200, ts = (c % 200) / 100, j = c % 100;
    g_B1[i] = att_a[(h * 100 + j) * 300 + ts * 100 + k];
}

__global__ void k_B2(const float* __restrict__ out_a) {
    int i = blockIdx.x * blockDim.x + threadIdx.x;
    if (i >= D2 * 400) return;
    int k = i / 400, c = i % 400;
    int ts = c / 200, j = c % 200;
    g_B2[i] = out_a[j * 600 + ts * 200 + k];
}

__global__ void k_w1(const float* __restrict__ rel_emb,
                     const float* __restrict__ att_a) {
    int i = blockIdx.x * blockDim.x + threadIdx.x;
    if (i >= 2 * NR * D1) return;
    int h = i / (NR * D1);
    int rem = i % (NR * D1);
    int r = rem / D1, j = rem % D1;
    float s = 0.f;
#pragma unroll 4
    for (int k = 0; k < D1; k++)
        s += rel_emb[r * D1 + k] * att_a[(h * 100 + j) * 300 + 200 + k];
    g_w1[(h * NR + r) * D1 + j] = s;
}

__global__ void k_w2(const float* __restrict__ out_a) {
    int i = blockIdx.x * blockDim.x + threadIdx.x;
    if (i >= NR * D2) return;
    int r = i / D2, j = i % D2;
    float s = 0.f;
#pragma unroll 4
    for (int k = 0; k < D2; k++)
        s += g_or1[r * D2 + k] * out_a[j * 600 + 400 + k];
    g_w2[i] = s;
}

__global__ void k_u1(const float* __restrict__ att_a,
                     const float* __restrict__ att_a2) {
    int i = blockIdx.x * blockDim.x + threadIdx.x;
    if (i >= 4 * D1) return;
    int v = i / D1, k = i % D1;
    int h = v / 2, ts = v % 2;
    float s = 0.f;
#pragma unroll 4
    for (int j = 0; j < 100; j++)
        s += att_a[(h * 100 + j) * 300 + ts * 100 + k] * att_a2[h * 100 + j];
    g_u1[i] = s;
}

__global__ void k_u2(const float* __restrict__ out_a,
                     const float* __restrict__ out_a2) {
    int i = blockIdx.x * blockDim.x + threadIdx.x;
    if (i >= 2 * D2) return;
    int ts = i / D2, k = i % D2;
    float s = 0.f;
#pragma unroll 4
    for (int j = 0; j < 200; j++)
        s += out_a[j * 600 + ts * 200 + k] * out_a2[j];
    g_u2[i] = s;
}

__global__ void k_q1(const float* __restrict__ att_a2) {
    int i = blockIdx.x * blockDim.x + threadIdx.x;
    if (i >= 2 * NR) return;
    int h = i / NR, r = i % NR;
    float s = 0.f;
#pragma unroll 4
    for (int j = 0; j < D1; j++)
        s += g_w1[(h * NR + r) * D1 + j] * att_a2[h * 100 + j];
    g_q1[i] = s;
}

__global__ void k_q2(const float* __restrict__ out_a2) {
    int r = blockIdx.x * blockDim.x + threadIdx.x;
    if (r >= NR) return;
    float s = 0.f;
#pragma unroll 4
    for (int j = 0; j < D2; j++) s += g_w2[r * D2 + j] * out_a2[j];
    g_q2[r] = s;
}

__global__ void k_ortho(const float* __restrict__ att_a,
                        const float* __restrict__ out_a,
                        float* __restrict__ outp) {
    __shared__ float s0[256], s1[256], s2[256];
    int t = threadIdx.x;
    float total = 0.f;
    for (int m = 0; m < 3; m++) {
        const float* base = (m < 2) ? att_a + m * 30000 : out_a;
        int half = (m < 2) ? 15000 : 60000;
        float a00 = 0.f, a01 = 0.f, a11 = 0.f;
        for (int i = t; i < half; i += 256) {
            float x0 = base[i], x1 = base[half + i];
            a00 += x0 * x0; a01 += x0 * x1; a11 += x1 * x1;
        }
        s0[t] = a00; s1[t] = a01; s2[t] = a11;
        __syncthreads();
        for (int o = 128; o; o >>= 1) {
            if (t < o) { s0[t] += s0[t + o]; s1[t] += s1[t + o]; s2[t] += s2[t + o]; }
            __syncthreads();
        }
        if (t == 0) {
            float n0 = fmaxf(sqrtf(s0[0]), EPSV);
            float n1 = fmaxf(sqrtf(s2[0]), EPSV);
            float g00 = s0[0] / (n0 * n0);
            float g11 = s2[0] / (n1 * n1);
            float g01 = s1[0] / (n0 * n1);
            total += 0.01f * ((g00 - 1.f) * (g00 - 1.f) + (g11 - 1.f) * (g11 - 1.f) + 2.f * g01 * g01);
        }
        __syncthreads();
    }
    if (t == 0) outp[0] = total;
}

// ---------------- SGEMM: C[M,N] = A[M,K] @ B[K,N], 128x128x8, 8x8 microtile ----------------
__device__ __forceinline__ void sgemm_body(const float* __restrict__ A,
                                           const float* __restrict__ B,
                                           float* __restrict__ C,
                                           int M, int N, int K) {
    __shared__ float As[8][132];   // [k][m], padded: conflict-free, 16B-aligned rows
    __shared__ float Bs[8][128];   // [k][n]
    const int tid = threadIdx.x;
    const int bm = blockIdx.y * 128, bn = blockIdx.x * 128;
    const int tr = (tid >> 4) * 8;
    const int tc = (tid & 15) * 8;
    float acc[8][8];
#pragma unroll
    for (int i = 0; i < 8; i++)
#pragma unroll
        for (int j = 0; j < 8; j++) acc[i][j] = 0.f;

    for (int kk = 0; kk < K; kk += 8) {
#pragma unroll
        for (int i = tid; i < 1024; i += 256) {
            int k = i & 7, m = i >> 3;
            int gm = bm + m, gk = kk + k;
            As[k][m] = (gm < M && gk < K) ? A[(size_t)gm * K + gk] : 0.f;
        }
#pragma unroll
        for (int i = tid; i < 1024; i += 256) {
            int n = i & 127, k = i >> 7;
            int gn = bn + n, gk = kk + k;
            Bs[k][n] = (gn < N && gk < K) ? B[(size_t)gk * N + gn] : 0.f;
        }
        __syncthreads();
#pragma unroll
        for (int k = 0; k < 8; k++) {
            float4 a0 = *(const float4*)&As[k][tr];
            float4 a1 = *(const float4*)&As[k][tr + 4];
            float4 b0 = *(const float4*)&Bs[k][tc];
            float4 b1 = *(const float4*)&Bs[k][tc + 4];
            float a[8] = {a0.x, a0.y, a0.z, a0.w, a1.x, a1.y, a1.z, a1.w};
            float b[8] = {b0.x, b0.y, b0.z, b0.w, b1.x, b1.y, b1.z, b1.w};
#pragma unroll
            for (int i = 0; i < 8; i++)
#pragma unroll
                for (int j = 0; j < 8; j++) acc[i][j] += a[i] * b[j];
        }
        __syncthreads();
    }
#pragma unroll
    for (int i = 0; i < 8; i++) {
        int gm = bm + tr + i;
        if (gm >= M) continue;
#pragma unroll
        for (int j = 0; j < 8; j++) {
            int gn = bn + tc + j;
            if (gn < N) C[(size_t)gm * N + gn] = acc[i][j];
        }
    }
}

__global__ void __launch_bounds__(256) k_sgemm_Y1() { sgemm_body(g_ent, g_B1, g_Y1, NN, 400, D1); }
__global__ void __launch_bounds__(256) k_sgemm_Y2() { sgemm_body(g_x, g_B2, g_Y2, NN, 400, D2); }
__global__ void __launch_bounds__(256) k_sgemm_pre(const float* __restrict__ W) {
    sgemm_body(g_ent, W, g_pre, NN, D2, D1);
}

// ---------------- attention scalars ----------------
__global__ void k_p1() {
    __shared__ float su[400];
    for (int i = threadIdx.x; i < 400; i += blockDim.x) su[i] = g_u1[i];
    __syncthreads();
    int n = (blockIdx.x * blockDim.x + threadIdx.x) >> 5;
    int lane = threadIdx.x & 31;
    if (n >= NN) return;
    float e[4];
#pragma unroll
    for (int j = 0; j < 4; j++) {
        int d = lane + 32 * j;
        e[j] = (d < D1) ? g_ent[n * D1 + d] : 0.f;
    }
#pragma unroll
    for (int v = 0; v < 4; v++) {
        float s = 0.f;
#pragma unroll
        for (int j = 0; j < 4; j++) {
            int d = lane + 32 * j;
            if (d < D1) s += e[j] * su[v * D1 + d];
        }
#pragma unroll
        for (int o = 16; o; o >>= 1) s += __shfl_xor_sync(0xffffffffu, s, o);
        if (lane == 0) g_p1[n * 4 + v] = s;
    }
}

__global__ void k_p2() {
    __shared__ float su[400];
    for (int i = threadIdx.x; i < 400; i += blockDim.x) su[i] = g_u2[i];
    __syncthreads();
    int n = (blockIdx.x * blockDim.x + threadIdx.x) >> 5;
    int lane = threadIdx.x & 31;
    if (n >= NN) return;
    float e[7];
#pragma unroll
    for (int j = 0; j < 7; j++) {
        int d = lane + 32 * j;
        e[j] = (d < D2) ? g_x[(size_t)n * D2 + d] : 0.f;
    }
#pragma unroll
    for (int v = 0; v < 2; v++) {
        float s = 0.f;
#pragma unroll
        for (int j = 0; j < 7; j++) {
            int d = lane + 32 * j;
            if (d < D2) s += e[j] * su[v * D2 + d];
        }
#pragma unroll
        for (int o = 16; o; o >>= 1) s += __shfl_xor_sync(0xffffffffu, s, o);
        if (lane == 0) g_p2[n * 2 + v] = s;
    }
}

__global__ void k_ee1() {
    int e = blockIdx.x * blockDim.x + threadIdx.x;
    if (e >= ET) return;
    int t = g_tgt[e], s = g_src[e], ra = g_relA[e], rb = g_relB[e];
#pragma unroll
    for (int h = 0; h < 2; h++) {
        float p = g_p1[t * 4 + 2 * h] + g_p1[s * 4 + 2 * h + 1] + g_q1[h * NR + ra];
        if (rb >= 0) p += g_q1[h * NR + rb];
        float z = (p >= 0.f) ? p : 0.2f * p;
        g_ee1[e * 2 + h] = expf(-z);
    }
}

__global__ void k_ee2() {
    int e = blockIdx.x * blockDim.x + threadIdx.x;
    if (e >= ET) return;
    int t = g_tgt[e], s = g_src[e], ra = g_relA[e], rb = g_relB[e];
    float p = g_p2[t * 2] + g_p2[s * 2 + 1] + g_q2[ra];
    if (rb >= 0) p += g_q2[rb];
    float z = (p >= 0.f) ? p : 0.2f * p;
    g_ee2[e] = expf(-z);
}

// ---------------- CSR gather aggregation ----------------
__global__ void k_gather1() {
    int n = (blockIdx.x * blockDim.x + threadIdx.x) >> 5;
    int lane = threadIdx.x & 31;
    if (n >= NN) return;
    int start = g_rowptr[n], end = g_rowptr[n + 1];
#pragma unroll
    for (int h = 0; h < 2; h++) {
        float acc[4] = {0.f, 0.f, 0.f, 0.f};
        float es = 0.f;
        for (int i = start; i < end; i++) {
            int e = g_csr[i];
            float ee = g_ee1[e * 2 + h];
            int s = g_src[e], ra = g_relA[e], rb = g_relB[e];
            const float* ys = &g_Y1[(size_t)s * 400 + h * 200 + 100];
            const float* wa = &g_w1[(h * NR + ra) * D1];
            const float* wb = (rb >= 0) ? &g_w1[(h * NR + rb) * D1] : wa;
            float scaleB = (rb >= 0) ? 1.f : 0.f;
#pragma unroll
            for (int j = 0; j < 4; j++) {
                int d = lane + 32 * j;
                if (d < D1) {
                    float v = ys[d] + wa[d] + scaleB * wb[d];
                    acc[j] += ee * v;
                }
            }
            es += ee;
        }
        float inv = (end > start) ? 1.f / es : 0.f;
#pragma unroll
        for (int j = 0; j < 4; j++) {
            int d = lane + 32 * j;
            if (d < D1) {
                float o = 0.f;
                if (end > start) {
                    float v = g_Y1[(size_t)n * 400 + h * 200 + d] + acc[j] * inv;
                    o = (v > 0.f) ? v : expm1f(v);
                }
                g_x[(size_t)n * D2 + h * D1 + d] = o;
            }
        }
    }
}

__global__ void k_gather2() {
    int n = (blockIdx.x * blockDim.x + threadIdx.x) >> 5;
    int lane = threadIdx.x & 31;
    if (n >= NN) return;
    int start = g_rowptr[n], end = g_rowptr[n + 1];
    float acc[7] = {0.f, 0.f, 0.f, 0.f, 0.f, 0.f, 0.f};
    float es = 0.f;
    for (int i = start; i < end; i++) {
        int e = g_csr[i];
        float ee = g_ee2[e];
        int s = g_src[e], ra = g_relA[e], rb = g_relB[e];
        const float* ys = &g_Y2[(size_t)s * 400 + 200];
        const float* wa = &g_w2[ra * D2];
        const float* wb = (rb >= 0) ? &g_w2[rb * D2] : wa;
        float scaleB = (rb >= 0) ? 1.f : 0.f;
#pragma unroll
        for (int j = 0; j < 7; j++) {
            int d = lane + 32 * j;
            if (d < D2) {
                float v = ys[d] + wa[d] + scaleB * wb[d];
                acc[j] += ee * v;
            }
        }
        es += ee;
    }
    float inv = (end > start) ? 1.f / es : 0.f;
#pragma unroll
    for (int j = 0; j < 7; j++) {
        int d = lane + 32 * j;
        if (d < D2) {
            float o = 0.f;
            if (end > start) o = g_Y2[(size_t)n * 400 + d] + acc[j] * inv;
            g_h2[(size_t)n * D2 + d] = o;
        }
    }
}

// ---------------- final: residual + l2norm ----------------
__global__ void k_final(float* __restrict__ outp) {
    int n = (blockIdx.x * blockDim.x + threadIdx.x) >> 5;
    int lane = threadIdx.x & 31;
    if (n >= NN) return;
    float msk = g_mask[n];
    float v[7]; float ss = 0.f;
#pragma unroll
    for (int j = 0; j < 7; j++) {
        int d = lane + 32 * j;
        v[j] = 0.f;
        if (d < D2) {
            v[j] = g_pre[(size_t)n * D2 + d] + msk * g_h2[(size_t)n * D2 + d];
            ss += v[j] * v[j];
        }
    }
#pragma unroll
    for (int o = 16; o; o >>= 1) ss += __shfl_xor_sync(0xffffffffu, ss, o);
    float inv = 1.f / fmaxf(sqrtf(ss), EPSV);
#pragma unroll
    for (int j = 0; j < 7; j++) {
        int d = lane + 32 * j;
        if (d < D2) outp[(size_t)n * D2 + d] = v[j] * inv;
    }
}

// ---------------- launch ----------------
extern "C" void kernel_launch(void* const* d_in, const int* in_sizes, int n_in,
                              void* d_out, int out_size) {
    const int*   edge_list    = (const int*)d_in[0];
    const int*   edge_type    = (const int*)d_in[1];
    const int*   batch_inputs = (const int*)d_in[2];
    const int*   nhop         = (const int*)d_in[3];
    const float* ent_emb      = (const float*)d_in[4];
    const float* rel_emb      = (const float*)d_in[5];
    const float* W_ent        = (const float*)d_in[6];
    const float* W_rel        = (const float*)d_in[7];
    const float* att_a        = (const float*)d_in[8];
    const float* att_a2       = (const float*)d_in[9];
    const float* out_a        = (const float*)d_in[10];
    const float* out_a2       = (const float*)d_in[11];
    float* out = (float*)d_out;

    // graph structure + mask
    k_init<<<(NN + 255) / 256, 256>>>();
    k_build_edges<<<(ET + 255) / 256, 256>>>(edge_list, edge_type, nhop);
    k_scan<<<1, 1024>>>();
    k_fill<<<(ET + 255) / 256, 256>>>();
    k_mask_set<<<(NB + 255) / 256, 256>>>(batch_inputs);

    // embeddings + small precomputes
    k_norm_ent<<<NN / 8, 256>>>(ent_emb);
    k_or1<<<(NR * D2 + 255) / 256, 256>>>(rel_emb, W_rel, out);
    k_B1<<<(D1 * 400 + 255) / 256, 256>>>(att_a);
    k_B2<<<(D2 * 400 + 255) / 256, 256>>>(out_a);
    k_w1<<<(2 * NR * D1 + 255) / 256, 256>>>(rel_emb, att_a);
    k_u1<<<2, 256>>>(att_a, att_a2);
    k_u2<<<2, 256>>>(out_a, out_a2);
    k_w2<<<(NR * D2 + 255) / 256, 256>>>(out_a);
    k_q1<<<4, 256>>>(att_a2);
    k_q2<<<2, 256>>>(out_a2);
    k_ortho<<<1, 256>>>(att_a, out_a, out + (size_t)NN * D2 + NR * D2);

    // layer 1
    k_sgemm_Y1<<<dim3(4, 313), 256>>>();
    k_p1<<<NN / 8, 256>>>();
    k_ee1<<<(ET + 255) / 256, 256>>>();
    k_gather1<<<NN / 8, 256>>>();

    // layer 2
    k_sgemm_Y2<<<dim3(4, 313), 256>>>();
    k_p2<<<NN / 8, 256>>>();
    k_ee2<<<(ET + 255) / 256, 256>>>();
    k_gather2<<<NN / 8, 256>>>();

    // final
    k_sgemm_pre<<<dim3(2, 313), 256>>>(W_ent);
    k_final<<<NN / 8, 256>>>(out);
}

// round 2
// speedup vs baseline: 1.4488x; 1.4488x over previous
#include <cuda_runtime.h>
#include <mma.h>
#include <math.h>
#include <stdint.h>

using namespace nvcuda;

#define NN 40000
#define MPAD 40064
#define NR 474
#define E1 100000
#define ET 130000
#define D1 100
#define D2 200
#define NB 8192
#define EPSV 1e-12f

// ---------------- device scratch ----------------
__device__ float g_ent[NN * D1];
__device__ float g_Y1[(size_t)MPAD * 400];    // [n][h*200 + ts*100 + j]
__device__ float g_Y2[(size_t)MPAD * 400];    // [n][ts*200 + j]
__device__ float g_x[NN * D2];
__device__ float g_h2[NN * D2];
__device__ float g_pre[(size_t)MPAD * 208];   // padded cols (200 -> 208)
__device__ float g_p1[NN * 4];
__device__ float g_p2[NN * 2];
__device__ float g_mask[NN];
__device__ int4  g_edge[ET];                  // (t, s, ra, rb)
__device__ float g_ee1[ET * 2];
__device__ float g_ee2[ET];
__device__ int   g_cnt[NN];
__device__ int   g_rowptr[NN + 1];
__device__ int   g_fill[NN];
__device__ int   g_csr[ET];
__device__ float g_B1[D1 * 400];
__device__ float g_B2[D2 * 400];
__device__ float g_w1[2 * NR * D1];
__device__ float g_w2[NR * D2];
__device__ float g_q1[2 * NR];
__device__ float g_q2[NR];
__device__ float g_u1[4 * D1];
__device__ float g_u2[2 * D2];
__device__ float g_or1[NR * D2];

// ---------------- init / graph build ----------------
__global__ void k_init() {
    int i = blockIdx.x * blockDim.x + threadIdx.x;
    if (i < NN) { g_cnt[i] = 0; g_mask[i] = 0.f; }
}

__global__ void k_build_edges(const int* __restrict__ edge_list,
                              const int* __restrict__ edge_type,
                              const int* __restrict__ nhop) {
    int e = blockIdx.x * blockDim.x + threadIdx.x;
    if (e >= ET) return;
    int t, s, ra, rb;
    if (e < E1) {
        t = edge_list[e]; s = edge_list[E1 + e];
        ra = edge_type[e]; rb = -1;
    } else {
        int i = e - E1;
        t = nhop[i * 4 + 3]; s = nhop[i * 4 + 0];
        ra = nhop[i * 4 + 1]; rb = nhop[i * 4 + 2];
    }
    g_edge[e] = make_int4(t, s, ra, rb);
    atomicAdd(&g_cnt[t], 1);
}

__global__ void k_scan() {   // 1 block, 1024 threads, 40 elems each
    int t = threadIdx.x;
    int base = t * 40;
    int s = 0;
#pragma unroll 8
    for (int i = 0; i < 40; i++) { int idx = base + i; if (idx < NN) s += g_cnt[idx]; }
    int lane = t & 31, w = t >> 5;
    int v = s;
#pragma unroll
    for (int off = 1; off < 32; off <<= 1) {
        int n = __shfl_up_sync(0xffffffffu, v, off);
        if (lane >= off) v += n;
    }
    __shared__ int ws[32];
    if (lane == 31) ws[w] = v;
    __syncthreads();
    if (w == 0) {
        int x = ws[lane];
#pragma unroll
        for (int off = 1; off < 32; off <<= 1) {
            int n = __shfl_up_sync(0xffffffffu, x, off);
            if (lane >= off) x += n;
        }
        ws[lane] = x;
    }
    __syncthreads();
    int run = v - s + ((w > 0) ? ws[w - 1] : 0);
#pragma unroll 8
    for (int i = 0; i < 40; i++) {
        int idx = base + i;
        if (idx < NN) { g_rowptr[idx] = run; g_fill[idx] = run; run += g_cnt[idx]; }
    }
    if (t == 1023) g_rowptr[NN] = run;
}

__global__ void k_fill() {
    int e = blockIdx.x * blockDim.x + threadIdx.x;
    if (e >= ET) return;
    int t = g_edge[e].x;
    int pos = atomicAdd(&g_fill[t], 1);
    g_csr[pos] = e;
}

__global__ void k_mask_set(const int* __restrict__ batch_inputs) {
    int i = blockIdx.x * blockDim.x + threadIdx.x;
    if (i < NB) g_mask[batch_inputs[i * 3 + 2]] = 1.0f;
}

// ---------------- small prep kernels ----------------
__global__ void k_norm_ent(const float* __restrict__ emb) {
    int w = (blockIdx.x * blockDim.x + threadIdx.x) >> 5;
    int lane = threadIdx.x & 31;
    if (w >= NN) return;
    float v[4]; float ss = 0.f;
#pragma unroll
    for (int j = 0; j < 4; j++) {
        int d = lane + 32 * j;
        v[j] = (d < D1) ? emb[w * D1 + d] : 0.f;
        ss += v[j] * v[j];
    }
#pragma unroll
    for (int o = 16; o; o >>= 1) ss += __shfl_xor_sync(0xffffffffu, ss, o);
    float inv = 1.f / fmaxf(sqrtf(ss), EPSV);
#pragma unroll
    for (int j = 0; j < 4; j++) {
        int d = lane + 32 * j;
        if (d < D1) g_ent[w * D1 + d] = v[j] * inv;
    }
}

__global__ void k_or1(const float* __restrict__ rel_emb,
                      const float* __restrict__ W_rel,
                      float* __restrict__ out) {
    int i = blockIdx.x * blockDim.x + threadIdx.x;
    if (i >= NR * D2) return;
    int r = i / D2, d = i % D2;
    float s = 0.f;
#pragma unroll 4
    for (int k = 0; k < D1; k++) s += rel_emb[r * D1 + k] * W_rel[k * D2 + d];
    g_or1[i] = s;
    out[NN * D2 + i] = s;
}

__global__ void k_B1(const float* __restrict__ att_a) {
    int i = blockIdx.x * blockDim.x + threadIdx.x;
    if (i >= D1 * 400) return;
    int k = i / 400, c = i % 400;
    int h = c / 200, ts = (c % 200) / 100, j = c % 100;
    g_B1[i] = att_a[(h * 100 + j) * 300 + ts * 100 + k];
}

__global__ void k_B2(const float* __restrict__ out_a) {
    int i = blockIdx.x * blockDim.x + threadIdx.x;
    if (i >= D2 * 400) return;
    int k = i / 400, c = i % 400;
    int ts = c / 200, j = c % 200;
    g_B2[i] = out_a[j * 600 + ts * 200 + k];
}

__global__ void k_w1(const float* __restrict__ rel_emb,
                     const float* __restrict__ att_a) {
    int i = blockIdx.x * blockDim.x + threadIdx.x;
    if (i >= 2 * NR * D1) return;
    int h = i / (NR * D1);
    int rem = i % (NR * D1);
    int r = rem / D1, j = rem % D1;
    float s = 0.f;
#pragma unroll 4
    for (int k = 0; k < D1; k++)
        s += rel_emb[r * D1 + k] * att_a[(h * 100 + j) * 300 + 200 + k];
    g_w1[(h * NR + r) * D1 + j] = s;
}

__global__ void k_w2(const float* __restrict__ out_a) {
    int i = blockIdx.x * blockDim.x + threadIdx.x;
    if (i >= NR * D2) return;
    int r = i / D2, j = i % D2;
    float s = 0.f;
#pragma unroll 4
    for (int k = 0; k < D2; k++)
        s += g_or1[r * D2 + k] * out_a[j * 600 + 400 + k];
    g_w2[i] = s;
}

__global__ void k_u1(const float* __restrict__ att_a,
                     const float* __restrict__ att_a2) {
    int i = blockIdx.x * blockDim.x + threadIdx.x;
    if (i >= 4 * D1) return;
    int v = i / D1, k = i % D1;
    int h = v / 2, ts = v % 2;
    float s = 0.f;
#pragma unroll 4
    for (int j = 0; j < 100; j++)
        s += att_a[(h * 100 + j) * 300 + ts * 100 + k] * att_a2[h * 100 + j];
    g_u1[i] = s;
}

__global__ void k_u2(const float* __restrict__ out_a,
                     const float* __restrict__ out_a2) {
    int i = blockIdx.x * blockDim.x + threadIdx.x;
    if (i >= 2 * D2) return;
    int ts = i / D2, k = i % D2;
    float s = 0.f;
#pragma unroll 4
    for (int j = 0; j < 200; j++)
        s += out_a[j * 600 + ts * 200 + k] * out_a2[j];
    g_u2[i] = s;
}

__global__ void k_q1(const float* __restrict__ att_a2) {
    int i = blockIdx.x * blockDim.x + threadIdx.x;
    if (i >= 2 * NR) return;
    int h = i / NR, r = i % NR;
    float s = 0.f;
#pragma unroll 4
    for (int j = 0; j < D1; j++)
        s += g_w1[(h * NR + r) * D1 + j] * att_a2[h * 100 + j];
    g_q1[i] = s;
}

__global__ void k_q2(const float* __restrict__ out_a2) {
    int r = blockIdx.x * blockDim.x + threadIdx.x;
    if (r >= NR) return;
    float s = 0.f;
#pragma unroll 4
    for (int j = 0; j < D2; j++) s += g_w2[r * D2 + j] * out_a2[j];
    g_q2[r] = s;
}

__global__ void k_ortho(const float* __restrict__ att_a,
                        const float* __restrict__ out_a,
                        float* __restrict__ outp) {
    __shared__ float s0[256], s1[256], s2[256];
    int t = threadIdx.x;
    float total = 0.f;
    for (int m = 0; m < 3; m++) {
        const float* base = (m < 2) ? att_a + m * 30000 : out_a;
        int half = (m < 2) ? 15000 : 60000;
        float a00 = 0.f, a01 = 0.f, a11 = 0.f;
        for (int i = t; i < half; i += 256) {
            float x0 = base[i], x1 = base[half + i];
            a00 += x0 * x0; a01 += x0 * x1; a11 += x1 * x1;
        }
        s0[t] = a00; s1[t] = a01; s2[t] = a11;
        __syncthreads();
        for (int o = 128; o; o >>= 1) {
            if (t < o) { s0[t] += s0[t + o]; s1[t] += s1[t + o]; s2[t] += s2[t + o]; }
            __syncthreads();
        }
        if (t == 0) {
            float n0 = fmaxf(sqrtf(s0[0]), EPSV);
            float n1 = fmaxf(sqrtf(s2[0]), EPSV);
            float g00 = s0[0] / (n0 * n0);
            float g11 = s2[0] / (n1 * n1);
            float g01 = s1[0] / (n0 * n1);
            total += 0.01f * ((g00 - 1.f) * (g00 - 1.f) + (g11 - 1.f) * (g11 - 1.f) + 2.f * g01 * g01);
        }
        __syncthreads();
    }
    if (t == 0) outp[0] = total;
}

// ---------------- tf32 wmma GEMM: C[M,Npad] = A[M,K] @ B[K,Nreal] ----------------
// BM=128, BN=128, BK=32. 8 warps in 4(m) x 2(n). Warp tile 32x64 = 2x4 wmma tiles.
// Stores are full 16x16 tiles into padded C (MPAD rows, Npad cols, Npad%16==0).
__device__ __forceinline__ void gemm_tf32(const float* __restrict__ A, int M, int K,
                                          const float* __restrict__ B, int Nreal,
                                          float* __restrict__ C, int Npad) {
    __shared__ float As[128][40];
    __shared__ float Bs[32][136];
    const int tid = threadIdx.x;
    const int bm = blockIdx.y * 128, bn = blockIdx.x * 128;
    const int warpId = tid >> 5;
    const int wm = (warpId >> 1) * 32;
    const int wn = (warpId & 1) * 64;

    wmma::fragment<wmma::accumulator, 16, 16, 8, float> c[2][4];
#pragma unroll
    for (int i = 0; i < 2; i++)
#pragma unroll
        for (int j = 0; j < 4; j++) wmma::fill_fragment(c[i][j], 0.f);

    for (int kk = 0; kk < K; kk += 32) {
#pragma unroll
        for (int i = 0; i < 16; i++) {
            int idx = tid + i * 256;
            int m = idx >> 5, k = idx & 31;
            int gm = bm + m, gk = kk + k;
            As[m][k] = (gm < M && gk < K) ? __ldg(&A[(size_t)gm * K + gk]) : 0.f;
        }
#pragma unroll
        for (int i = 0; i < 16; i++) {
            int idx = tid + i * 256;
            int k = idx >> 7, n = idx & 127;
            int gk = kk + k, gn = bn + n;
            Bs[k][n] = (gk < K && gn < Nreal) ? __ldg(&B[(size_t)gk * Nreal + gn]) : 0.f;
        }
        __syncthreads();
#pragma unroll
        for (int k8 = 0; k8 < 32; k8 += 8) {
            wmma::fragment<wmma::matrix_a, 16, 16, 8, wmma::precision::tf32, wmma::row_major> a[2];
            wmma::fragment<wmma::matrix_b, 16, 16, 8, wmma::precision::tf32, wmma::row_major> b[4];
#pragma unroll
            for (int i = 0; i < 2; i++) {
                wmma::load_matrix_sync(a[i], &As[wm + i * 16][k8], 40);
#pragma unroll
                for (int t = 0; t < a[i].num_elements; t++)
                    a[i].x[t] = wmma::__float_to_tf32(a[i].x[t]);
            }
#pragma unroll
            for (int j = 0; j < 4; j++) {
                wmma::load_matrix_sync(b[j], &Bs[k8][wn + j * 16], 136);
#pragma unroll
                for (int t = 0; t < b[j].num_elements; t++)
                    b[j].x[t] = wmma::__float_to_tf32(b[j].x[t]);
            }
#pragma unroll
            for (int i = 0; i < 2; i++)
#pragma unroll
                for (int j = 0; j < 4; j++)
                    wmma::mma_sync(c[i][j], a[i], b[j], c[i][j]);
        }
        __syncthreads();
    }
#pragma unroll
    for (int i = 0; i < 2; i++) {
        int gm = bm + wm + i * 16;
#pragma unroll
        for (int j = 0; j < 4; j++) {
            int gn = bn + wn + j * 16;
            if (gn + 16 <= Npad)
                wmma::store_matrix_sync(&C[(size_t)gm * Npad + gn], c[i][j], Npad,
                                        wmma::mem_row_major);
        }
    }
}

__global__ void __launch_bounds__(256) k_gemm_Y1() {
    gemm_tf32(g_ent, NN, D1, g_B1, 400, g_Y1, 400);
}
__global__ void __launch_bounds__(256) k_gemm_Y2() {
    gemm_tf32(g_x, NN, D2, g_B2, 400, g_Y2, 400);
}
__global__ void __launch_bounds__(256) k_gemm_pre(const float* __restrict__ W) {
    gemm_tf32(g_ent, NN, D1, W, D2, g_pre, 208);
}

// ---------------- attention scalars ----------------
__global__ void k_p1() {
    __shared__ float su[400];
    for (int i = threadIdx.x; i < 400; i += blockDim.x) su[i] = g_u1[i];
    __syncthreads();
    int n = (blockIdx.x * blockDim.x + threadIdx.x) >> 5;
    int lane = threadIdx.x & 31;
    if (n >= NN) return;
    float e[4];
#pragma unroll
    for (int j = 0; j < 4; j++) {
        int d = lane + 32 * j;
        e[j] = (d < D1) ? g_ent[n * D1 + d] : 0.f;
    }
#pragma unroll
    for (int v = 0; v < 4; v++) {
        float s = 0.f;
#pragma unroll
        for (int j = 0; j < 4; j++) {
            int d = lane + 32 * j;
            if (d < D1) s += e[j] * su[v * D1 + d];
        }
#pragma unroll
        for (int o = 16; o; o >>= 1) s += __shfl_xor_sync(0xffffffffu, s, o);
        if (lane == 0) g_p1[n * 4 + v] = s;
    }
}

__global__ void k_p2() {
    __shared__ float su[400];
    for (int i = threadIdx.x; i < 400; i += blockDim.x) su[i] = g_u2[i];
    __syncthreads();
    int n = (blockIdx.x * blockDim.x + threadIdx.x) >> 5;
    int lane = threadIdx.x & 31;
    if (n >= NN) return;
    float e[7];
#pragma unroll
    for (int j = 0; j < 7; j++) {
        int d = lane + 32 * j;
        e[j] = (d < D2) ? g_x[(size_t)n * D2 + d] : 0.f;
    }
#pragma unroll
    for (int v = 0; v < 2; v++) {
        float s = 0.f;
#pragma unroll
        for (int j = 0; j < 7; j++) {
            int d = lane + 32 * j;
            if (d < D2) s += e[j] * su[v * D2 + d];
        }
#pragma unroll
        for (int o = 16; o; o >>= 1) s += __shfl_xor_sync(0xffffffffu, s, o);
        if (lane == 0) g_p2[n * 2 + v] = s;
    }
}

__global__ void k_ee1() {
    int e = blockIdx.x * blockDim.x + threadIdx.x;
    if (e >= ET) return;
    int4 ed = g_edge[e];
#pragma unroll
    for (int h = 0; h < 2; h++) {
        float p = g_p1[ed.x * 4 + 2 * h] + g_p1[ed.y * 4 + 2 * h + 1] + g_q1[h * NR + ed.z];
        if (ed.w >= 0) p += g_q1[h * NR + ed.w];
        float z = (p >= 0.f) ? p : 0.2f * p;
        g_ee1[e * 2 + h] = expf(-z);
    }
}

__global__ void k_ee2() {
    int e = blockIdx.x * blockDim.x + threadIdx.x;
    if (e >= ET) return;
    int4 ed = g_edge[e];
    float p = g_p2[ed.x * 2] + g_p2[ed.y * 2 + 1] + g_q2[ed.z];
    if (ed.w >= 0) p += g_q2[ed.w];
    float z = (p >= 0.f) ? p : 0.2f * p;
    g_ee2[e] = expf(-z);
}

// ---------------- CSR gather aggregation ----------------
__global__ void k_gather1() {
    int n = (blockIdx.x * blockDim.x + threadIdx.x) >> 5;
    int lane = threadIdx.x & 31;
    if (n >= NN) return;
    int start = g_rowptr[n], end = g_rowptr[n + 1];
    float acc[2][4] = {{0.f, 0.f, 0.f, 0.f}, {0.f, 0.f, 0.f, 0.f}};
    float es[2] = {0.f, 0.f};
    for (int i = start; i < end; i++) {
        int e = g_csr[i];
        int4 ed = g_edge[e];
        float ee0 = g_ee1[e * 2], ee1 = g_ee1[e * 2 + 1];
        const float* ybase = &g_Y1[(size_t)ed.y * 400];
        float sB = (ed.w >= 0) ? 1.f : 0.f;
        int rb = (ed.w >= 0) ? ed.w : ed.z;
#pragma unroll
        for (int j = 0; j < 4; j++) {
            int d = lane + 32 * j;
            if (d < D1) {
                float wa0 = g_w1[(0 * NR + ed.z) * D1 + d];
                float wb0 = g_w1[(0 * NR + rb) * D1 + d];
                float wa1 = g_w1[(1 * NR + ed.z) * D1 + d];
                float wb1 = g_w1[(1 * NR + rb) * D1 + d];
                acc[0][j] += ee0 * (ybase[100 + d] + wa0 + sB * wb0);
                acc[1][j] += ee1 * (ybase[300 + d] + wa1 + sB * wb1);
            }
        }
        es[0] += ee0; es[1] += ee1;
    }
    bool has = (end > start);
    float inv0 = has ? 1.f / es[0] : 0.f;
    float inv1 = has ? 1.f / es[1] : 0.f;
#pragma unroll
    for (int j = 0; j < 4; j++) {
        int d = lane + 32 * j;
        if (d < D1) {
            float o0 = 0.f, o1 = 0.f;
            if (has) {
                float v0 = g_Y1[(size_t)n * 400 + d] + acc[0][j] * inv0;
                float v1 = g_Y1[(size_t)n * 400 + 200 + d] + acc[1][j] * inv1;
                o0 = (v0 > 0.f) ? v0 : expm1f(v0);
                o1 = (v1 > 0.f) ? v1 : expm1f(v1);
            }
            g_x[(size_t)n * D2 + d] = o0;
            g_x[(size_t)n * D2 + 100 + d] = o1;
        }
    }
}

__global__ void k_gather2() {
    int n = (blockIdx.x * blockDim.x + threadIdx.x) >> 5;
    int lane = threadIdx.x & 31;
    if (n >= NN) return;
    int start = g_rowptr[n], end = g_rowptr[n + 1];
    float acc[7] = {0.f, 0.f, 0.f, 0.f, 0.f, 0.f, 0.f};
    float es = 0.f;
    for (int i = start; i < end; i++) {
        int e = g_csr[i];
        int4 ed = g_edge[e];
        float ee = g_ee2[e];
        const float* ys = &g_Y2[(size_t)ed.y * 400 + 200];
        float sB = (ed.w >= 0) ? 1.f : 0.f;
        int rb = (ed.w >= 0) ? ed.w : ed.z;
#pragma unroll
        for (int j = 0; j < 7; j++) {
            int d = lane + 32 * j;
            if (d < D2) {
                float v = ys[d] + g_w2[ed.z * D2 + d] + sB * g_w2[rb * D2 + d];
                acc[j] += ee * v;
            }
        }
        es += ee;
    }
    float inv = (end > start) ? 1.f / es : 0.f;
#pragma unroll
    for (int j = 0; j < 7; j++) {
        int d = lane + 32 * j;
        if (d < D2) {
            float o = 0.f;
            if (end > start) o = g_Y2[(size_t)n * 400 + d] + acc[j] * inv;
            g_h2[(size_t)n * D2 + d] = o;
        }
    }
}

// ---------------- final: residual + l2norm ----------------
__global__ void k_final(float* __restrict__ outp) {
    int n = (blockIdx.x * blockDim.x + threadIdx.x) >> 5;
    int lane = threadIdx.x & 31;
    if (n >= NN) return;
    float msk = g_mask[n];
    float v[7]; float ss = 0.f;
#pragma unroll
    for (int j = 0; j < 7; j++) {
        int d = lane + 32 * j;
        v[j] = 0.f;
        if (d < D2) {
            v[j] = g_pre[(size_t)n * 208 + d] + msk * g_h2[(size_t)n * D2 + d];
            ss += v[j] * v[j];
        }
    }
#pragma unroll
    for (int o = 16; o; o >>= 1) ss += __shfl_xor_sync(0xffffffffu, ss, o);
    float inv = 1.f / fmaxf(sqrtf(ss), EPSV);
#pragma unroll
    for (int j = 0; j < 7; j++) {
        int d = lane + 32 * j;
        if (d < D2) outp[(size_t)n * D2 + d] = v[j] * inv;
    }
}

// ---------------- launch ----------------
extern "C" void kernel_launch(void* const* d_in, const int* in_sizes, int n_in,
                              void* d_out, int out_size) {
    const int*   edge_list    = (const int*)d_in[0];
    const int*   edge_type    = (const int*)d_in[1];
    const int*   batch_inputs = (const int*)d_in[2];
    const int*   nhop         = (const int*)d_in[3];
    const float* ent_emb      = (const float*)d_in[4];
    const float* rel_emb      = (const float*)d_in[5];
    const float* W_ent        = (const float*)d_in[6];
    const float* W_rel        = (const float*)d_in[7];
    const float* att_a        = (const float*)d_in[8];
    const float* att_a2       = (const float*)d_in[9];
    const float* out_a        = (const float*)d_in[10];
    const float* out_a2       = (const float*)d_in[11];
    float* out = (float*)d_out;

    // graph structure + mask
    k_init<<<(NN + 255) / 256, 256>>>();
    k_build_edges<<<(ET + 255) / 256, 256>>>(edge_list, edge_type, nhop);
    k_scan<<<1, 1024>>>();
    k_fill<<<(ET + 255) / 256, 256>>>();
    k_mask_set<<<(NB + 255) / 256, 256>>>(batch_inputs);

    // embeddings + small precomputes
    k_norm_ent<<<NN / 8, 256>>>(ent_emb);
    k_or1<<<(NR * D2 + 255) / 256, 256>>>(rel_emb, W_rel, out);
    k_B1<<<(D1 * 400 + 255) / 256, 256>>>(att_a);
    k_B2<<<(D2 * 400 + 255) / 256, 256>>>(out_a);
    k_w1<<<(2 * NR * D1 + 255) / 256, 256>>>(rel_emb, att_a);
    k_u1<<<2, 256>>>(att_a, att_a2);
    k_u2<<<2, 256>>>(out_a, out_a2);
    k_w2<<<(NR * D2 + 255) / 256, 256>>>(out_a);
    k_q1<<<4, 256>>>(att_a2);
    k_q2<<<2, 256>>>(out_a2);
    k_ortho<<<1, 256>>>(att_a, out_a, out + (size_t)NN * D2 + NR * D2);

    // layer 1
    k_gemm_Y1<<<dim3(4, 313), 256>>>();
    k_p1<<<NN / 8, 256>>>();
    k_ee1<<<(ET + 255) / 256, 256>>>();
    k_gather1<<<NN / 8, 256>>>();

    // layer 2
    k_gemm_Y2<<<dim3(4, 313), 256>>>();
    k_p2<<<NN / 8, 256>>>();
    k_ee2<<<(ET + 255) / 256, 256>>>();
    k_gather2<<<NN / 8, 256>>>();

    // final
    k_gemm_pre<<<dim3(2, 313), 256>>>(W_ent);
    k_final<<<NN / 8, 256>>>(out);
}

// round 3
// speedup vs baseline: 2.1025x; 1.4512x over previous
#include <cuda_runtime.h>
#include <mma.h>
#include <math.h>
#include <stdint.h>

using namespace nvcuda;

#define NN 40000
#define MPAD 40064
#define NR 474
#define E1 100000
#define ET 130000
#define D1 100
#define D2 200
#define NB 8192
#define EPSV 1e-12f

// ---------------- device scratch ----------------
__device__ float g_ent[NN * D1];
__device__ float g_Y1[(size_t)MPAD * 400];
__device__ float g_Y2[(size_t)MPAD * 400];
__device__ float g_x[NN * D2];
__device__ float g_h2[NN * D2];
__device__ float g_pre[(size_t)MPAD * 208];
__device__ float g_p1[NN * 4];
__device__ float g_p2[NN * 2];
__device__ float g_mask[NN];
__device__ int4  g_edge[ET];
__device__ int   g_cnt[NN];
__device__ int   g_rowptr[NN + 1];
__device__ int   g_fill[NN];
__device__ int   g_csr[ET];
__device__ float g_B1[D1 * 400];
__device__ float g_B2[D2 * 400];
__device__ float g_w1[2 * NR * D1];
__device__ float g_w2[NR * D2];
__device__ float g_q1[2 * NR];
__device__ float g_q2[NR];
__device__ float g_u1[4 * D1];
__device__ float g_u2[2 * D2];
__device__ float g_or1[NR * D2];

// ---------------- launch 1: init ----------------
__global__ void k_init() {
    int i = blockIdx.x * blockDim.x + threadIdx.x;
    if (i < NN) { g_cnt[i] = 0; g_mask[i] = 0.f; }
}

// ---------------- launch 2: mega1 (256 threads) ----------------
#define M1_BUILD 508
#define M1_MASK  (M1_BUILD + 32)
#define M1_B1    (M1_MASK + 157)
#define M1_B2    (M1_B1 + 313)
#define M1_W1    (M1_B2 + 371)
#define M1_U1    (M1_W1 + 2)
#define M1_U2    (M1_U1 + 2)
#define M1_OR1   (M1_U2 + 371)
#define M1_ORTHO (M1_OR1 + 1)
#define M1_NORM  (M1_ORTHO + 5000)

__global__ void __launch_bounds__(256) k_mega1(
    const int* __restrict__ edge_list, const int* __restrict__ edge_type,
    const int* __restrict__ nhop, const int* __restrict__ batch_inputs,
    const float* __restrict__ emb, const float* __restrict__ rel_emb,
    const float* __restrict__ W_rel, const float* __restrict__ att_a,
    const float* __restrict__ att_a2, const float* __restrict__ out_a,
    const float* __restrict__ out_a2, float* __restrict__ out) {
    __shared__ float s0[256], s1[256], s2[256];
    int b = blockIdx.x, tid = threadIdx.x;
    if (b < M1_BUILD) {
        int e = b * 256 + tid;
        if (e >= ET) return;
        int t, s, ra, rb;
        if (e < E1) {
            t = edge_list[e]; s = edge_list[E1 + e];
            ra = edge_type[e]; rb = -1;
        } else {
            int i = e - E1;
            t = nhop[i * 4 + 3]; s = nhop[i * 4 + 0];
            ra = nhop[i * 4 + 1]; rb = nhop[i * 4 + 2];
        }
        g_edge[e] = make_int4(t, s, ra, rb);
        atomicAdd(&g_cnt[t], 1);
    } else if (b < M1_MASK) {
        int i = (b - M1_BUILD) * 256 + tid;
        if (i < NB) g_mask[batch_inputs[i * 3 + 2]] = 1.0f;
    } else if (b < M1_B1) {
        int i = (b - M1_MASK) * 256 + tid;
        if (i >= D1 * 400) return;
        int k = i / 400, c = i % 400;
        int h = c / 200, ts = (c % 200) / 100, j = c % 100;
        g_B1[i] = att_a[(h * 100 + j) * 300 + ts * 100 + k];
    } else if (b < M1_B2) {
        int i = (b - M1_B1) * 256 + tid;
        if (i >= D2 * 400) return;
        int k = i / 400, c = i % 400;
        int ts = c / 200, j = c % 200;
        g_B2[i] = out_a[j * 600 + ts * 200 + k];
    } else if (b < M1_W1) {
        int i = (b - M1_B2) * 256 + tid;
        if (i >= 2 * NR * D1) return;
        int h = i / (NR * D1);
        int rem = i % (NR * D1);
        int r = rem / D1, j = rem % D1;
        float s = 0.f;
#pragma unroll 4
        for (int k = 0; k < D1; k++)
            s += rel_emb[r * D1 + k] * att_a[(h * 100 + j) * 300 + 200 + k];
        g_w1[(h * NR + r) * D1 + j] = s;
    } else if (b < M1_U1) {
        int i = (b - M1_W1) * 256 + tid;
        if (i >= 4 * D1) return;
        int v = i / D1, k = i % D1;
        int h = v / 2, ts = v % 2;
        float s = 0.f;
#pragma unroll 4
        for (int j = 0; j < 100; j++)
            s += att_a[(h * 100 + j) * 300 + ts * 100 + k] * att_a2[h * 100 + j];
        g_u1[i] = s;
    } else if (b < M1_U2) {
        int i = (b - M1_U1) * 256 + tid;
        if (i >= 2 * D2) return;
        int ts = i / D2, k = i % D2;
        float s = 0.f;
#pragma unroll 4
        for (int j = 0; j < 200; j++)
            s += out_a[j * 600 + ts * 200 + k] * out_a2[j];
        g_u2[i] = s;
    } else if (b < M1_OR1) {
        int i = (b - M1_U2) * 256 + tid;
        if (i >= NR * D2) return;
        int r = i / D2, d = i % D2;
        float s = 0.f;
#pragma unroll 4
        for (int k = 0; k < D1; k++) s += rel_emb[r * D1 + k] * W_rel[k * D2 + d];
        g_or1[i] = s;
        out[NN * D2 + i] = s;
    } else if (b < M1_ORTHO) {
        float total = 0.f;
        for (int m = 0; m < 3; m++) {
            const float* base = (m < 2) ? att_a + m * 30000 : out_a;
            int half = (m < 2) ? 15000 : 60000;
            float a00 = 0.f, a01 = 0.f, a11 = 0.f;
            for (int i = tid; i < half; i += 256) {
                float x0 = base[i], x1 = base[half + i];
                a00 += x0 * x0; a01 += x0 * x1; a11 += x1 * x1;
            }
            s0[tid] = a00; s1[tid] = a01; s2[tid] = a11;
            __syncthreads();
            for (int o = 128; o; o >>= 1) {
                if (tid < o) { s0[tid] += s0[tid + o]; s1[tid] += s1[tid + o]; s2[tid] += s2[tid + o]; }
                __syncthreads();
            }
            if (tid == 0) {
                float n0 = fmaxf(sqrtf(s0[0]), EPSV);
                float n1 = fmaxf(sqrtf(s2[0]), EPSV);
                float g00 = s0[0] / (n0 * n0);
                float g11 = s2[0] / (n1 * n1);
                float g01 = s1[0] / (n0 * n1);
                total += 0.01f * ((g00 - 1.f) * (g00 - 1.f) + (g11 - 1.f) * (g11 - 1.f) + 2.f * g01 * g01);
            }
            __syncthreads();
        }
        if (tid == 0) out[NN * D2 + NR * D2] = total;
    } else {
        int n = (b - M1_ORTHO) * 8 + (tid >> 5);
        int lane = tid & 31;
        if (n >= NN) return;
        float v[4]; float ss = 0.f;
#pragma unroll
        for (int j = 0; j < 4; j++) {
            int d = lane + 32 * j;
            v[j] = (d < D1) ? emb[n * D1 + d] : 0.f;
            ss += v[j] * v[j];
        }
#pragma unroll
        for (int o = 16; o; o >>= 1) ss += __shfl_xor_sync(0xffffffffu, ss, o);
        float inv = 1.f / fmaxf(sqrtf(ss), EPSV);
#pragma unroll
        for (int j = 0; j < 4; j++) {
            int d = lane + 32 * j;
            if (d < D1) g_ent[n * D1 + d] = v[j] * inv;
        }
    }
}

// ---------------- launch 3: mega2 (1024 threads): scan | w2 | q1 | p1 ----------------
#define M2_W2 94
#define M2_Q1 95
#define M2_P1 1345

__global__ void __launch_bounds__(1024) k_mega2(const float* __restrict__ out_a,
                                                const float* __restrict__ att_a2) {
    __shared__ int ws[32];
    __shared__ float su[400];
    int b = blockIdx.x, t = threadIdx.x;
    if (b == 0) {
        int base = t * 40;
        int s = 0;
#pragma unroll 8
        for (int i = 0; i < 40; i++) { int idx = base + i; if (idx < NN) s += g_cnt[idx]; }
        int lane = t & 31, w = t >> 5;
        int v = s;
#pragma unroll
        for (int off = 1; off < 32; off <<= 1) {
            int n = __shfl_up_sync(0xffffffffu, v, off);
            if (lane >= off) v += n;
        }
        if (lane == 31) ws[w] = v;
        __syncthreads();
        if (w == 0) {
            int x = ws[lane];
#pragma unroll
            for (int off = 1; off < 32; off <<= 1) {
                int n = __shfl_up_sync(0xffffffffu, x, off);
                if (lane >= off) x += n;
            }
            ws[lane] = x;
        }
        __syncthreads();
        int run = v - s + ((w > 0) ? ws[w - 1] : 0);
#pragma unroll 8
        for (int i = 0; i < 40; i++) {
            int idx = base + i;
            if (idx < NN) { g_rowptr[idx] = run; g_fill[idx] = run; run += g_cnt[idx]; }
        }
        if (t == 1023) g_rowptr[NN] = run;
    } else if (b < M2_W2) {
        int i = (b - 1) * 1024 + t;
        if (i >= NR * D2) return;
        int r = i / D2, j = i % D2;
        float s = 0.f;
#pragma unroll 4
        for (int k = 0; k < D2; k++)
            s += g_or1[r * D2 + k] * out_a[j * 600 + 400 + k];
        g_w2[i] = s;
    } else if (b < M2_Q1) {
        int i = t;
        if (i >= 2 * NR) return;
        int h = i / NR, r = i % NR;
        float s = 0.f;
#pragma unroll 4
        for (int j = 0; j < D1; j++)
            s += g_w1[(h * NR + r) * D1 + j] * att_a2[h * 100 + j];
        g_q1[i] = s;
    } else {
        for (int i = t; i < 400; i += 1024) su[i] = g_u1[i];
        __syncthreads();
        int n = (b - M2_Q1) * 32 + (t >> 5);
        int lane = t & 31;
        if (n >= NN) return;
        float e[4];
#pragma unroll
        for (int j = 0; j < 4; j++) {
            int d = lane + 32 * j;
            e[j] = (d < D1) ? g_ent[n * D1 + d] : 0.f;
        }
#pragma unroll
        for (int v = 0; v < 4; v++) {
            float s = 0.f;
#pragma unroll
            for (int j = 0; j < 4; j++) {
                int d = lane + 32 * j;
                if (d < D1) s += e[j] * su[v * D1 + d];
            }
#pragma unroll
            for (int o = 16; o; o >>= 1) s += __shfl_xor_sync(0xffffffffu, s, o);
            if (lane == 0) g_p1[n * 4 + v] = s;
        }
    }
}

// ---------------- launch 4: mega3 (512 threads): fill | q2 ----------------
__global__ void __launch_bounds__(512) k_mega3(const float* __restrict__ out_a2) {
    int b = blockIdx.x, t = threadIdx.x;
    if (b < 254) {
        int e = b * 512 + t;
        if (e >= ET) return;
        int tg = g_edge[e].x;
        int pos = atomicAdd(&g_fill[tg], 1);
        g_csr[pos] = e;
    } else {
        int r = t;
        if (r >= NR) return;
        float s = 0.f;
#pragma unroll 4
        for (int j = 0; j < D2; j++) s += g_w2[r * D2 + j] * out_a2[j];
        g_q2[r] = s;
    }
}

// ---------------- tf32 wmma GEMM v2: BM=128 BN=80 BK=32 ----------------
// tf32 rounding at smem-store; register-staged prefetch; 8 warps x (16 rows x 80 cols)
__device__ __forceinline__ void gemm_tf32(const float* __restrict__ A, int M, int K,
                                          const float* __restrict__ B, int N,
                                          float* __restrict__ C, int Npad) {
    __shared__ __align__(16) float As[128][40];
    __shared__ __align__(16) float Bs[32][88];
    const int tid = threadIdx.x;
    const int bm = blockIdx.y * 128, bn = blockIdx.x * 80;
    const int wm = (tid >> 5) * 16;

    wmma::fragment<wmma::accumulator, 16, 16, 8, float> c[5];
#pragma unroll
    for (int j = 0; j < 5; j++) wmma::fill_fragment(c[j], 0.f);

    float4 ra[4], rb[3];
    // mapping A: idx = q*256 + tid; m = idx>>3; kq = idx&7 (4-float chunk)
    // mapping B: idx = q*256 + tid (idx<640); k = idx/20; c4 = (idx%20)*4
    {
        const float4 z = make_float4(0.f, 0.f, 0.f, 0.f);
#pragma unroll
        for (int q = 0; q < 4; q++) {
            int idx = q * 256 + tid;
            int m = idx >> 3, kq = (idx & 7) * 4;
            int gm = bm + m;
            ra[q] = (gm < M && kq < K) ? *(const float4*)&A[(size_t)gm * K + kq] : z;
        }
#pragma unroll
        for (int q = 0; q < 3; q++) {
            int idx = q * 256 + tid;
            rb[q] = z;
            if (idx < 640) {
                int k = idx / 20, c4 = (idx % 20) * 4;
                int gn = bn + c4;
                if (k < K && gn < N) rb[q] = *(const float4*)&B[(size_t)k * N + gn];
            }
        }
    }

    for (int kk = 0; kk < K; kk += 32) {
        // store (with tf32 rounding) into smem
#pragma unroll
        for (int q = 0; q < 4; q++) {
            int idx = q * 256 + tid;
            int m = idx >> 3, kq = (idx & 7) * 4;
            float4 v = ra[q];
            v.x = wmma::__float_to_tf32(v.x);
            v.y = wmma::__float_to_tf32(v.y);
            v.z = wmma::__float_to_tf32(v.z);
            v.w = wmma::__float_to_tf32(v.w);
            *(float4*)&As[m][kq] = v;
        }
#pragma unroll
        for (int q = 0; q < 3; q++) {
            int idx = q * 256 + tid;
            if (idx < 640) {
                int k = idx / 20, c4 = (idx % 20) * 4;
                float4 v = rb[q];
                v.x = wmma::__float_to_tf32(v.x);
                v.y = wmma::__float_to_tf32(v.y);
                v.z = wmma::__float_to_tf32(v.z);
                v.w = wmma::__float_to_tf32(v.w);
                *(float4*)&Bs[k][c4] = v;
            }
        }
        __syncthreads();
        // prefetch next tile into regs
        int kn = kk + 32;
        if (kn < K) {
            const float4 z = make_float4(0.f, 0.f, 0.f, 0.f);
#pragma unroll
            for (int q = 0; q < 4; q++) {
                int idx = q * 256 + tid;
                int m = idx >> 3, kq = (idx & 7) * 4;
                int gm = bm + m, gk = kn + kq;
                ra[q] = (gm < M && gk < K) ? *(const float4*)&A[(size_t)gm * K + gk] : z;
            }
#pragma unroll
            for (int q = 0; q < 3; q++) {
                int idx = q * 256 + tid;
                rb[q] = z;
                if (idx < 640) {
                    int k = idx / 20, c4 = (idx % 20) * 4;
                    int gk = kn + k, gn = bn + c4;
                    if (gk < K && gn < N) rb[q] = *(const float4*)&B[(size_t)gk * N + gn];
                }
            }
        }
        // compute
#pragma unroll
        for (int k8 = 0; k8 < 32; k8 += 8) {
            wmma::fragment<wmma::matrix_a, 16, 16, 8, wmma::precision::tf32, wmma::row_major> a;
            wmma::load_matrix_sync(a, &As[wm][k8], 40);
#pragma unroll
            for (int j = 0; j < 5; j++) {
                wmma::fragment<wmma::matrix_b, 16, 16, 8, wmma::precision::tf32, wmma::row_major> bfr;
                wmma::load_matrix_sync(bfr, &Bs[k8][j * 16], 88);
                wmma::mma_sync(c[j], a, bfr, c[j]);
            }
        }
        __syncthreads();
    }
#pragma unroll
    for (int j = 0; j < 5; j++) {
        int gn = bn + j * 16;
        if (gn + 16 <= Npad)
            wmma::store_matrix_sync(&C[(size_t)(bm + wm) * Npad + gn], c[j], Npad,
                                    wmma::mem_row_major);
    }
}

__global__ void __launch_bounds__(256) k_gemm_Y1() {
    gemm_tf32(g_ent, NN, D1, g_B1, 400, g_Y1, 400);
}
__global__ void __launch_bounds__(256) k_gemm_Y2() {
    gemm_tf32(g_x, NN, D2, g_B2, 400, g_Y2, 400);
}
__global__ void __launch_bounds__(256) k_gemm_pre(const float* __restrict__ W) {
    gemm_tf32(g_ent, NN, D1, W, D2, g_pre, 208);
}

// ---------------- gather1: ee1 + aggregation + elu + p2, fused ----------------
__global__ void k_gather1() {
    __shared__ float su2[400];
    for (int i = threadIdx.x; i < 400; i += blockDim.x) su2[i] = g_u2[i];
    __syncthreads();
    int n = (blockIdx.x * blockDim.x + threadIdx.x) >> 5;
    int lane = threadIdx.x & 31;
    if (n >= NN) return;
    int start = g_rowptr[n], end = g_rowptr[n + 1];
    float pt0 = g_p1[n * 4 + 0], pt1 = g_p1[n * 4 + 2];
    float acc[2][4] = {{0.f, 0.f, 0.f, 0.f}, {0.f, 0.f, 0.f, 0.f}};
    float es0 = 0.f, es1 = 0.f;
    for (int i = start; i < end; i++) {
        int e = g_csr[i];
        int4 ed = g_edge[e];
        float sB = (ed.w >= 0) ? 1.f : 0.f;
        int rb = (ed.w >= 0) ? ed.w : ed.z;
        float l0 = pt0 + g_p1[ed.y * 4 + 1] + g_q1[ed.z] + sB * g_q1[rb];
        float l1 = pt1 + g_p1[ed.y * 4 + 3] + g_q1[NR + ed.z] + sB * g_q1[NR + rb];
        float z0 = (l0 >= 0.f) ? l0 : 0.2f * l0;
        float z1 = (l1 >= 0.f) ? l1 : 0.2f * l1;
        float ee0 = expf(-z0), ee1 = expf(-z1);
        const float* ybase = &g_Y1[(size_t)ed.y * 400];
#pragma unroll
        for (int j = 0; j < 4; j++) {
            int d = lane + 32 * j;
            if (d < D1) {
                float wa0 = g_w1[ed.z * D1 + d];
                float wb0 = g_w1[rb * D1 + d];
                float wa1 = g_w1[(NR + ed.z) * D1 + d];
                float wb1 = g_w1[(NR + rb) * D1 + d];
                acc[0][j] += ee0 * (ybase[100 + d] + wa0 + sB * wb0);
                acc[1][j] += ee1 * (ybase[300 + d] + wa1 + sB * wb1);
            }
        }
        es0 += ee0; es1 += ee1;
    }
    bool has = (end > start);
    float inv0 = has ? 1.f / es0 : 0.f;
    float inv1 = has ? 1.f / es1 : 0.f;
    float pa = 0.f, pb = 0.f;
#pragma unroll
    for (int j = 0; j < 4; j++) {
        int d = lane + 32 * j;
        if (d < D1) {
            float o0 = 0.f, o1 = 0.f;
            if (has) {
                float v0 = g_Y1[(size_t)n * 400 + d] + acc[0][j] * inv0;
                float v1 = g_Y1[(size_t)n * 400 + 200 + d] + acc[1][j] * inv1;
                o0 = (v0 > 0.f) ? v0 : expm1f(v0);
                o1 = (v1 > 0.f) ? v1 : expm1f(v1);
            }
            g_x[(size_t)n * D2 + d] = o0;
            g_x[(size_t)n * D2 + 100 + d] = o1;
            pa += o0 * su2[d] + o1 * su2[100 + d];
            pb += o0 * su2[200 + d] + o1 * su2[300 + d];
        }
    }
#pragma unroll
    for (int o = 16; o; o >>= 1) {
        pa += __shfl_xor_sync(0xffffffffu, pa, o);
        pb += __shfl_xor_sync(0xffffffffu, pb, o);
    }
    if (lane == 0) { g_p2[n * 2] = pa; g_p2[n * 2 + 1] = pb; }
}

// ---------------- gather2: ee2 + aggregation, fused ----------------
__global__ void k_gather2() {
    int n = (blockIdx.x * blockDim.x + threadIdx.x) >> 5;
    int lane = threadIdx.x & 31;
    if (n >= NN) return;
    int start = g_rowptr[n], end = g_rowptr[n + 1];
    float pt = g_p2[n * 2];
    float acc[7] = {0.f, 0.f, 0.f, 0.f, 0.f, 0.f, 0.f};
    float es = 0.f;
    for (int i = start; i < end; i++) {
        int e = g_csr[i];
        int4 ed = g_edge[e];
        float sB = (ed.w >= 0) ? 1.f : 0.f;
        int rb = (ed.w >= 0) ? ed.w : ed.z;
        float l = pt + g_p2[ed.y * 2 + 1] + g_q2[ed.z] + sB * g_q2[rb];
        float z = (l >= 0.f) ? l : 0.2f * l;
        float ee = expf(-z);
        const float* ys = &g_Y2[(size_t)ed.y * 400 + 200];
#pragma unroll
        for (int j = 0; j < 7; j++) {
            int d = lane + 32 * j;
            if (d < D2) {
                float v = ys[d] + g_w2[ed.z * D2 + d] + sB * g_w2[rb * D2 + d];
                acc[j] += ee * v;
            }
        }
        es += ee;
    }
    float inv = (end > start) ? 1.f / es : 0.f;
#pragma unroll
    for (int j = 0; j < 7; j++) {
        int d = lane + 32 * j;
        if (d < D2) {
            float o = 0.f;
            if (end > start) o = g_Y2[(size_t)n * 400 + d] + acc[j] * inv;
            g_h2[(size_t)n * D2 + d] = o;
        }
    }
}

// ---------------- final: residual + l2norm ----------------
__global__ void k_final(float* __restrict__ outp) {
    int n = (blockIdx.x * blockDim.x + threadIdx.x) >> 5;
    int lane = threadIdx.x & 31;
    if (n >= NN) return;
    float msk = g_mask[n];
    float v[7]; float ss = 0.f;
#pragma unroll
    for (int j = 0; j < 7; j++) {
        int d = lane + 32 * j;
        v[j] = 0.f;
        if (d < D2) {
            v[j] = g_pre[(size_t)n * 208 + d] + msk * g_h2[(size_t)n * D2 + d];
            ss += v[j] * v[j];
        }
    }
#pragma unroll
    for (int o = 16; o; o >>= 1) ss += __shfl_xor_sync(0xffffffffu, ss, o);
    float inv = 1.f / fmaxf(sqrtf(ss), EPSV);
#pragma unroll
    for (int j = 0; j < 7; j++) {
        int d = lane + 32 * j;
        if (d < D2) outp[(size_t)n * D2 + d] = v[j] * inv;
    }
}

// ---------------- launch ----------------
extern "C" void kernel_launch(void* const* d_in, const int* in_sizes, int n_in,
                              void* d_out, int out_size) {
    const int*   edge_list    = (const int*)d_in[0];
    const int*   edge_type    = (const int*)d_in[1];
    const int*   batch_inputs = (const int*)d_in[2];
    const int*   nhop         = (const int*)d_in[3];
    const float* ent_emb      = (const float*)d_in[4];
    const float* rel_emb      = (const float*)d_in[5];
    const float* W_ent        = (const float*)d_in[6];
    const float* W_rel        = (const float*)d_in[7];
    const float* att_a        = (const float*)d_in[8];
    const float* att_a2       = (const float*)d_in[9];
    const float* out_a        = (const float*)d_in[10];
    const float* out_a2       = (const float*)d_in[11];
    float* out = (float*)d_out;

    k_init<<<(NN + 255) / 256, 256>>>();
    k_mega1<<<M1_NORM, 256>>>(edge_list, edge_type, nhop, batch_inputs,
                              ent_emb, rel_emb, W_rel, att_a, att_a2,
                              out_a, out_a2, out);
    k_mega2<<<M2_P1, 1024>>>(out_a, att_a2);
    k_mega3<<<255, 512>>>(out_a2);
    k_gemm_Y1<<<dim3(5, 313), 256>>>();
    k_gather1<<<NN / 8, 256>>>();
    k_gemm_Y2<<<dim3(5, 313), 256>>>();
    k_gather2<<<NN / 8, 256>>>();
    k_gemm_pre<<<dim3(3, 313), 256>>>(W_ent);
    k_final<<<NN / 8, 256>>>(out);
}

// round 4
// speedup vs baseline: 2.1763x; 1.0351x over previous
#include <cuda_runtime.h>
#include <mma.h>
#include <math.h>
#include <stdint.h>

using namespace nvcuda;

#define NN 40000
#define MPAD 40064
#define NR 474
#define E1 100000
#define ET 130000
#define D1 100
#define D2 200
#define NB 8192
#define EPSV 1e-12f

// ---------------- device scratch ----------------
__device__ __align__(16) float g_ent[NN * D1];
__device__ __align__(16) float g_Y1[(size_t)MPAD * 400];   // [n][ts*200 + h*100 + j]
__device__ __align__(16) float g_Y2[(size_t)MPAD * 400];   // [n][ts*200 + j]
__device__ __align__(16) float g_x[NN * D2];
__device__ __align__(16) float g_pre[(size_t)MPAD * 208];
__device__ float g_p1[NN * 4];
__device__ float g_p2[NN * 2];
__device__ float g_mask[NN];
__device__ int4  g_edge[ET];
__device__ int   g_rank[ET];
__device__ int   g_cnt[NN];
__device__ int   g_rowptr[NN + 1];
__device__ int   g_csr[ET];
__device__ __align__(16) float g_B1[D1 * 400];
__device__ __align__(16) float g_B2[D2 * 400];
__device__ float g_w1[2 * NR * D1];
__device__ float g_w2[NR * D2];
__device__ float g_q1[2 * NR];
__device__ float g_q2[NR];
__device__ float g_u1[4 * D1];
__device__ float g_u2[2 * D2];
__device__ float g_or1[NR * D2];

__device__ __forceinline__ unsigned sm_u32(const void* p) {
    unsigned r;
    asm("{.reg .u64 t; cvta.to.shared.u64 t, %1; cvt.u32.u64 %0, t;}" : "=r"(r) : "l"(p));
    return r;
}
#define CPA16(dst, src, pred) \
    asm volatile("cp.async.cg.shared.global [%0], [%1], 16, %2;\n" \
                 :: "r"(dst), "l"(src), "r"((pred) ? 16 : 0))

// ---------------- launch 1: init ----------------
__global__ void k_init() {
    int i = blockIdx.x * blockDim.x + threadIdx.x;
    if (i < NN) { g_cnt[i] = 0; g_mask[i] = 0.f; }
}

// ---------------- launch 2: mega1 ----------------
#define M1_BUILD 508
#define M1_MASK  (M1_BUILD + 32)
#define M1_B1    (M1_MASK + 157)
#define M1_B2    (M1_B1 + 313)
#define M1_W1    (M1_B2 + 371)
#define M1_U1    (M1_W1 + 2)
#define M1_U2    (M1_U1 + 2)
#define M1_OR1   (M1_U2 + 371)
#define M1_ORTHO (M1_OR1 + 1)
#define M1_NORM  (M1_ORTHO + 5000)

__global__ void __launch_bounds__(256) k_mega1(
    const int* __restrict__ edge_list, const int* __restrict__ edge_type,
    const int* __restrict__ nhop, const int* __restrict__ batch_inputs,
    const float* __restrict__ emb, const float* __restrict__ rel_emb,
    const float* __restrict__ W_rel, const float* __restrict__ att_a,
    const float* __restrict__ att_a2, const float* __restrict__ out_a,
    const float* __restrict__ out_a2, float* __restrict__ out) {
    __shared__ float s0[256], s1[256], s2[256];
    int b = blockIdx.x, tid = threadIdx.x;
    if (b < M1_BUILD) {
        int e = b * 256 + tid;
        if (e >= ET) return;
        int t, s, ra, rb;
        if (e < E1) {
            t = edge_list[e]; s = edge_list[E1 + e];
            ra = edge_type[e]; rb = -1;
        } else {
            int i = e - E1;
            t = nhop[i * 4 + 3]; s = nhop[i * 4 + 0];
            ra = nhop[i * 4 + 1]; rb = nhop[i * 4 + 2];
        }
        g_edge[e] = make_int4(t, s, ra, rb);
        g_rank[e] = atomicAdd(&g_cnt[t], 1);
    } else if (b < M1_MASK) {
        int i = (b - M1_BUILD) * 256 + tid;
        if (i < NB) g_mask[batch_inputs[i * 3 + 2]] = 1.0f;
    } else if (b < M1_B1) {
        int i = (b - M1_MASK) * 256 + tid;
        if (i >= D1 * 400) return;
        int k = i / 400, c = i % 400;
        int ts = c / 200, h = (c % 200) / 100, j = c % 100;
        g_B1[i] = att_a[(h * 100 + j) * 300 + ts * 100 + k];
    } else if (b < M1_B2) {
        int i = (b - M1_B1) * 256 + tid;
        if (i >= D2 * 400) return;
        int k = i / 400, c = i % 400;
        int ts = c / 200, j = c % 200;
        g_B2[i] = out_a[j * 600 + ts * 200 + k];
    } else if (b < M1_W1) {
        int i = (b - M1_B2) * 256 + tid;
        if (i >= 2 * NR * D1) return;
        int h = i / (NR * D1);
        int rem = i % (NR * D1);
        int r = rem / D1, j = rem % D1;
        float s = 0.f;
#pragma unroll 4
        for (int k = 0; k < D1; k++)
            s += rel_emb[r * D1 + k] * att_a[(h * 100 + j) * 300 + 200 + k];
        g_w1[(h * NR + r) * D1 + j] = s;
    } else if (b < M1_U1) {
        int i = (b - M1_W1) * 256 + tid;
        if (i >= 4 * D1) return;
        int v = i / D1, k = i % D1;
        int h = v / 2, ts = v % 2;
        float s = 0.f;
#pragma unroll 4
        for (int j = 0; j < 100; j++)
            s += att_a[(h * 100 + j) * 300 + ts * 100 + k] * att_a2[h * 100 + j];
        g_u1[i] = s;
    } else if (b < M1_U2) {
        int i = (b - M1_U1) * 256 + tid;
        if (i >= 2 * D2) return;
        int ts = i / D2, k = i % D2;
        float s = 0.f;
#pragma unroll 4
        for (int j = 0; j < 200; j++)
            s += out_a[j * 600 + ts * 200 + k] * out_a2[j];
        g_u2[i] = s;
    } else if (b < M1_OR1) {
        int i = (b - M1_U2) * 256 + tid;
        if (i >= NR * D2) return;
        int r = i / D2, d = i % D2;
        float s = 0.f;
#pragma unroll 4
        for (int k = 0; k < D1; k++) s += rel_emb[r * D1 + k] * W_rel[k * D2 + d];
        g_or1[i] = s;
        out[NN * D2 + i] = s;
    } else if (b < M1_ORTHO) {
        float total = 0.f;
        for (int m = 0; m < 3; m++) {
            const float* base = (m < 2) ? att_a + m * 30000 : out_a;
            int half = (m < 2) ? 15000 : 60000;
            float a00 = 0.f, a01 = 0.f, a11 = 0.f;
            for (int i = tid; i < half; i += 256) {
                float x0 = base[i], x1 = base[half + i];
                a00 += x0 * x0; a01 += x0 * x1; a11 += x1 * x1;
            }
            s0[tid] = a00; s1[tid] = a01; s2[tid] = a11;
            __syncthreads();
            for (int o = 128; o; o >>= 1) {
                if (tid < o) { s0[tid] += s0[tid + o]; s1[tid] += s1[tid + o]; s2[tid] += s2[tid + o]; }
                __syncthreads();
            }
            if (tid == 0) {
                float n0 = fmaxf(sqrtf(s0[0]), EPSV);
                float n1 = fmaxf(sqrtf(s2[0]), EPSV);
                float g00 = s0[0] / (n0 * n0);
                float g11 = s2[0] / (n1 * n1);
                float g01 = s1[0] / (n0 * n1);
                total += 0.01f * ((g00 - 1.f) * (g00 - 1.f) + (g11 - 1.f) * (g11 - 1.f) + 2.f * g01 * g01);
            }
            __syncthreads();
        }
        if (tid == 0) out[NN * D2 + NR * D2] = total;
    } else {
        int n = (b - M1_ORTHO) * 8 + (tid >> 5);
        int lane = tid & 31;
        if (n >= NN) return;
        float v[4]; float ss = 0.f;
#pragma unroll
        for (int j = 0; j < 4; j++) {
            int d = lane + 32 * j;
            v[j] = (d < D1) ? emb[n * D1 + d] : 0.f;
            ss += v[j] * v[j];
        }
#pragma unroll
        for (int o = 16; o; o >>= 1) ss += __shfl_xor_sync(0xffffffffu, ss, o);
        float inv = 1.f / fmaxf(sqrtf(ss), EPSV);
#pragma unroll
        for (int j = 0; j < 4; j++) {
            int d = lane + 32 * j;
            if (d < D1) g_ent[n * D1 + d] = v[j] * inv;
        }
    }
}

// ---------------- tf32 wmma GEMM: cp.async double-buffered, BM=128 BN=80 BK=32 ----------------
#define ASZ (128 * 40)
#define BSZ (32 * 88)
#define SMEM_GEMM ((2 * ASZ + 2 * BSZ) * 4)

__device__ __forceinline__ void gemm_stage(const float* __restrict__ A, int M, int K,
                                           const float* __restrict__ B, int N,
                                           int bm, int bn, int kk,
                                           unsigned aBase, unsigned bBase, int tid) {
#pragma unroll
    for (int q = 0; q < 4; q++) {
        int idx = q * 256 + tid;
        int m = idx >> 3, kq = (idx & 7) * 4;
        int gm = bm + m, gk = kk + kq;
        bool p = (gm < M) && (gk < K);
        const float* src = p ? &A[(size_t)gm * K + gk] : A;
        CPA16(aBase + (unsigned)(m * 40 + kq) * 4u, src, p);
    }
#pragma unroll
    for (int q = 0; q < 3; q++) {
        int idx = q * 256 + tid;
        if (idx < 640) {
            int k = idx / 20, c4 = (idx % 20) * 4;
            int gk = kk + k, gn = bn + c4;
            bool p = (gk < K) && (gn < N);
            const float* src = p ? &B[(size_t)gk * N + gn] : B;
            CPA16(bBase + (unsigned)(k * 88 + c4) * 4u, src, p);
        }
    }
    asm volatile("cp.async.commit_group;\n" ::);
}

__device__ __forceinline__ void gemm_tf32(const float* __restrict__ A, int M, int K,
                                          const float* __restrict__ B, int N,
                                          float* __restrict__ C, int Npad,
                                          int bx, int by, float* sm) {
    float* As = sm;
    float* Bs = sm + 2 * ASZ;
    const int tid = threadIdx.x;
    const int bm = by * 128, bn = bx * 80;
    const int wm = (tid >> 5) * 16;

    wmma::fragment<wmma::accumulator, 16, 16, 8, float> c[5];
#pragma unroll
    for (int j = 0; j < 5; j++) wmma::fill_fragment(c[j], 0.f);

    const int nk = (K + 31) / 32;
    gemm_stage(A, M, K, B, N, bm, bn, 0, sm_u32(As), sm_u32(Bs), tid);

    int buf = 0;
    for (int kt = 0; kt < nk; kt++) {
        asm volatile("cp.async.wait_group 0;\n" ::);
        __syncthreads();
        if (kt + 1 < nk)
            gemm_stage(A, M, K, B, N, bm, bn, (kt + 1) * 32,
                       sm_u32(As + (buf ^ 1) * ASZ), sm_u32(Bs + (buf ^ 1) * BSZ), tid);
        const float* Ab = As + buf * ASZ;
        const float* Bb = Bs + buf * BSZ;
#pragma unroll
        for (int k8 = 0; k8 < 32; k8 += 8) {
            wmma::fragment<wmma::matrix_a, 16, 16, 8, wmma::precision::tf32, wmma::row_major> a;
            wmma::load_matrix_sync(a, &Ab[wm * 40 + k8], 40);
#pragma unroll
            for (int t = 0; t < a.num_elements; t++) a.x[t] = wmma::__float_to_tf32(a.x[t]);
#pragma unroll
            for (int j = 0; j < 5; j++) {
                wmma::fragment<wmma::matrix_b, 16, 16, 8, wmma::precision::tf32, wmma::row_major> bf;
                wmma::load_matrix_sync(bf, &Bb[k8 * 88 + j * 16], 88);
#pragma unroll
                for (int t = 0; t < bf.num_elements; t++) bf.x[t] = wmma::__float_to_tf32(bf.x[t]);
                wmma::mma_sync(c[j], a, bf, c[j]);
            }
        }
        buf ^= 1;
    }
#pragma unroll
    for (int j = 0; j < 5; j++) {
        int gn = bn + j * 16;
        if (gn + 16 <= Npad)
            wmma::store_matrix_sync(&C[(size_t)(bm + wm) * Npad + gn], c[j], Npad,
                                    wmma::mem_row_major);
    }
}

// ---------------- launch 3: megaA: Y1 GEMM | pre GEMM | scan | w2 | q1 | p1 ----------------
#define A_Y1   1565
#define A_PRE  (A_Y1 + 939)
#define A_SCAN (A_PRE + 1)
#define A_W2   (A_SCAN + 371)
#define A_Q1   (A_W2 + 4)
#define A_P1   (A_Q1 + 5000)

__global__ void __launch_bounds__(256) k_megaA(const float* __restrict__ W_ent,
                                               const float* __restrict__ out_a,
                                               const float* __restrict__ att_a2) {
    extern __shared__ float dynsm[];
    __shared__ float su[400];
    __shared__ int ws[8];
    int b = blockIdx.x, t = threadIdx.x;
    if (b < A_Y1) {
        gemm_tf32(g_ent, NN, D1, g_B1, 400, g_Y1, 400, b % 5, b / 5, dynsm);
    } else if (b < A_PRE) {
        int bb = b - A_Y1;
        gemm_tf32(g_ent, NN, D1, W_ent, D2, g_pre, 208, bb % 3, bb / 3, dynsm);
    } else if (b < A_SCAN) {
        const int PER = 157;
        int base = t * PER;
        int s = 0;
        for (int i = 0; i < PER; i++) {
            int idx = base + i;
            if (idx < NN) s += g_cnt[idx];
        }
        int lane = t & 31, w = t >> 5;
        int v = s;
#pragma unroll
        for (int off = 1; off < 32; off <<= 1) {
            int nv = __shfl_up_sync(0xffffffffu, v, off);
            if (lane >= off) v += nv;
        }
        if (lane == 31) ws[w] = v;
        __syncthreads();
        if (w == 0 && lane < 8) {
            int x = ws[lane];
#pragma unroll
            for (int off = 1; off < 8; off <<= 1) {
                int nv = __shfl_up_sync(0x000000ffu, x, off);
                if (lane >= off) x += nv;
            }
            ws[lane] = x;
        }
        __syncthreads();
        int run = v - s + ((w > 0) ? ws[w - 1] : 0);
        for (int i = 0; i < PER; i++) {
            int idx = base + i;
            if (idx < NN) { g_rowptr[idx] = run; run += g_cnt[idx]; }
        }
        if (t == 255) g_rowptr[NN] = run;
    } else if (b < A_W2) {
        int i = (b - A_SCAN) * 256 + t;
        if (i >= NR * D2) return;
        int r = i / D2, j = i % D2;
        float s = 0.f;
#pragma unroll 4
        for (int k = 0; k < D2; k++)
            s += g_or1[r * D2 + k] * out_a[j * 600 + 400 + k];
        g_w2[i] = s;
    } else if (b < A_Q1) {
        int i = (b - A_W2) * 256 + t;
        if (i >= 2 * NR) return;
        int h = i / NR, r = i % NR;
        float s = 0.f;
#pragma unroll 4
        for (int j = 0; j < D1; j++)
            s += g_w1[(h * NR + r) * D1 + j] * att_a2[h * 100 + j];
        g_q1[i] = s;
    } else {
        for (int i = t; i < 400; i += 256) su[i] = g_u1[i];
        __syncthreads();
        int n = (b - A_Q1) * 8 + (t >> 5);
        int lane = t & 31;
        if (n >= NN) return;
        float e[4];
#pragma unroll
        for (int j = 0; j < 4; j++) {
            int d = lane + 32 * j;
            e[j] = (d < D1) ? g_ent[n * D1 + d] : 0.f;
        }
#pragma unroll
        for (int v = 0; v < 4; v++) {
            float s = 0.f;
#pragma unroll
            for (int j = 0; j < 4; j++) {
                int d = lane + 32 * j;
                if (d < D1) s += e[j] * su[v * D1 + d];
            }
#pragma unroll
            for (int o = 16; o; o >>= 1) s += __shfl_xor_sync(0xffffffffu, s, o);
            if (lane == 0) g_p1[n * 4 + v] = s;
        }
    }
}

// ---------------- launch 4: megaB: atomic-free fill | q2 ----------------
__global__ void __launch_bounds__(256) k_megaB(const float* __restrict__ out_a2) {
    int b = blockIdx.x, t = threadIdx.x;
    if (b < 508) {
        int e = b * 256 + t;
        if (e >= ET) return;
        int tg = g_edge[e].x;
        g_csr[g_rowptr[tg] + g_rank[e]] = e;
    } else {
        int r = (b - 508) * 256 + t;
        if (r >= NR) return;
        float s = 0.f;
#pragma unroll 4
        for (int j = 0; j < D2; j++) s += g_w2[r * D2 + j] * out_a2[j];
        g_q2[r] = s;
    }
}

// ---------------- gather1: ee1 + aggregation + elu + p2 ----------------
__global__ void k_gather1() {
    __shared__ float su2[400];
    for (int i = threadIdx.x; i < 400; i += blockDim.x) su2[i] = g_u2[i];
    __syncthreads();
    int n = (blockIdx.x * blockDim.x + threadIdx.x) >> 5;
    int lane = threadIdx.x & 31;
    if (n >= NN) return;
    int start = g_rowptr[n], end = g_rowptr[n + 1];
    float pt0 = g_p1[n * 4 + 0], pt1 = g_p1[n * 4 + 2];
    float acc[2][4] = {{0.f, 0.f, 0.f, 0.f}, {0.f, 0.f, 0.f, 0.f}};
    float es0 = 0.f, es1 = 0.f;
    for (int i = start; i < end; i++) {
        int e = g_csr[i];
        int4 ed = g_edge[e];
        float sB = (ed.w >= 0) ? 1.f : 0.f;
        int rb = (ed.w >= 0) ? ed.w : ed.z;
        float l0 = pt0 + g_p1[ed.y * 4 + 1] + g_q1[ed.z] + sB * g_q1[rb];
        float l1 = pt1 + g_p1[ed.y * 4 + 3] + g_q1[NR + ed.z] + sB * g_q1[NR + rb];
        float z0 = (l0 >= 0.f) ? l0 : 0.2f * l0;
        float z1 = (l1 >= 0.f) ? l1 : 0.2f * l1;
        float ee0 = expf(-z0), ee1 = expf(-z1);
        const float* ysrc = &g_Y1[(size_t)ed.y * 400 + 200];  // contiguous 800B: h0 then h1
#pragma unroll
        for (int j = 0; j < 4; j++) {
            int d = lane + 32 * j;
            if (d < D1) {
                float wa0 = g_w1[ed.z * D1 + d];
                float wb0 = g_w1[rb * D1 + d];
                float wa1 = g_w1[(NR + ed.z) * D1 + d];
                float wb1 = g_w1[(NR + rb) * D1 + d];
                acc[0][j] += ee0 * (ysrc[d] + wa0 + sB * wb0);
                acc[1][j] += ee1 * (ysrc[100 + d] + wa1 + sB * wb1);
            }
        }
        es0 += ee0; es1 += ee1;
    }
    bool has = (end > start);
    float inv0 = has ? 1.f / es0 : 0.f;
    float inv1 = has ? 1.f / es1 : 0.f;
    float pa = 0.f, pb = 0.f;
#pragma unroll
    for (int j = 0; j < 4; j++) {
        int d = lane + 32 * j;
        if (d < D1) {
            float o0 = 0.f, o1 = 0.f;
            if (has) {
                float v0 = g_Y1[(size_t)n * 400 + d] + acc[0][j] * inv0;
                float v1 = g_Y1[(size_t)n * 400 + 100 + d] + acc[1][j] * inv1;
                o0 = (v0 > 0.f) ? v0 : expm1f(v0);
                o1 = (v1 > 0.f) ? v1 : expm1f(v1);
            }
            g_x[(size_t)n * D2 + d] = o0;
            g_x[(size_t)n * D2 + 100 + d] = o1;
            pa += o0 * su2[d] + o1 * su2[100 + d];
            pb += o0 * su2[200 + d] + o1 * su2[300 + d];
        }
    }
#pragma unroll
    for (int o = 16; o; o >>= 1) {
        pa += __shfl_xor_sync(0xffffffffu, pa, o);
        pb += __shfl_xor_sync(0xffffffffu, pb, o);
    }
    if (lane == 0) { g_p2[n * 2] = pa; g_p2[n * 2 + 1] = pb; }
}

// ---------------- gemm Y2 ----------------
__global__ void __launch_bounds__(256) k_gemm_Y2() {
    extern __shared__ float dynsm[];
    gemm_tf32(g_x, NN, D2, g_B2, 400, g_Y2, 400, blockIdx.x, blockIdx.y, dynsm);
}

// ---------------- gather2 + final fused ----------------
__global__ void k_gather2final(float* __restrict__ outp) {
    int n = (blockIdx.x * blockDim.x + threadIdx.x) >> 5;
    int lane = threadIdx.x & 31;
    if (n >= NN) return;
    int start = g_rowptr[n], end = g_rowptr[n + 1];
    float pt = g_p2[n * 2];
    float acc[7] = {0.f, 0.f, 0.f, 0.f, 0.f, 0.f, 0.f};
    float es = 0.f;
    for (int i = start; i < end; i++) {
        int e = g_csr[i];
        int4 ed = g_edge[e];
        float sB = (ed.w >= 0) ? 1.f : 0.f;
        int rb = (ed.w >= 0) ? ed.w : ed.z;
        float l = pt + g_p2[ed.y * 2 + 1] + g_q2[ed.z] + sB * g_q2[rb];
        float z = (l >= 0.f) ? l : 0.2f * l;
        float ee = expf(-z);
        const float* ys = &g_Y2[(size_t)ed.y * 400 + 200];
#pragma unroll
        for (int j = 0; j < 7; j++) {
            int d = lane + 32 * j;
            if (d < D2) {
                float v = ys[d] + g_w2[ed.z * D2 + d] + sB * g_w2[rb * D2 + d];
                acc[j] += ee * v;
            }
        }
        es += ee;
    }
    bool has = (end > start);
    float inv = has ? 1.f / es : 0.f;
    float msk = g_mask[n];
    float v[7]; float ss = 0.f;
#pragma unroll
    for (int j = 0; j < 7; j++) {
        int d = lane + 32 * j;
        v[j] = 0.f;
        if (d < D2) {
            float h = has ? (g_Y2[(size_t)n * 400 + d] + acc[j] * inv) : 0.f;
            v[j] = g_pre[(size_t)n * 208 + d] + msk * h;
            ss += v[j] * v[j];
        }
    }
#pragma unroll
    for (int o = 16; o; o >>= 1) ss += __shfl_xor_sync(0xffffffffu, ss, o);
    float inv2 = 1.f / fmaxf(sqrtf(ss), EPSV);
#pragma unroll
    for (int j = 0; j < 7; j++) {
        int d = lane + 32 * j;
        if (d < D2) outp[(size_t)n * D2 + d] = v[j] * inv2;
    }
}

// ---------------- launch ----------------
extern "C" void kernel_launch(void* const* d_in, const int* in_sizes, int n_in,
                              void* d_out, int out_size) {
    const int*   edge_list    = (const int*)d_in[0];
    const int*   edge_type    = (const int*)d_in[1];
    const int*   batch_inputs = (const int*)d_in[2];
    const int*   nhop         = (const int*)d_in[3];
    const float* ent_emb      = (const float*)d_in[4];
    const float* rel_emb      = (const float*)d_in[5];
    const float* W_ent        = (const float*)d_in[6];
    const float* W_rel        = (const float*)d_in[7];
    const float* att_a        = (const float*)d_in[8];
    const float* att_a2       = (const float*)d_in[9];
    const float* out_a        = (const float*)d_in[10];
    const float* out_a2       = (const float*)d_in[11];
    float* out = (float*)d_out;

    cudaFuncSetAttribute(k_megaA, cudaFuncAttributeMaxDynamicSharedMemorySize, SMEM_GEMM);
    cudaFuncSetAttribute(k_gemm_Y2, cudaFuncAttributeMaxDynamicSharedMemorySize, SMEM_GEMM);

    k_init<<<(NN + 255) / 256, 256>>>();
    k_mega1<<<M1_NORM, 256>>>(edge_list, edge_type, nhop, batch_inputs,
                              ent_emb, rel_emb, W_rel, att_a, att_a2,
                              out_a, out_a2, out);
    k_megaA<<<A_P1, 256, SMEM_GEMM>>>(W_ent, out_a, att_a2);
    k_megaB<<<510, 256>>>(out_a2);
    k_gather1<<<NN / 8, 256>>>();
    k_gemm_Y2<<<dim3(5, 313), 256, SMEM_GEMM>>>();
    k_gather2final<<<NN / 8, 256>>>(out);
}

// round 5
// speedup vs baseline: 2.2541x; 1.0357x over previous
#include <cuda_runtime.h>
#include <mma.h>
#include <math.h>
#include <stdint.h>

using namespace nvcuda;

#define NN 40000
#define MPAD 40192
#define NR 474
#define E1 100000
#define ET 130000
#define D1 100
#define D2 200
#define NB 8192
#define EPSV 1e-12f

// ---------------- device scratch ----------------
__device__ __align__(16) float g_ent[NN * D1];     // exact (for p1)
__device__ __align__(16) float g_entR[NN * D1];    // tf32-rounded (GEMM A)
__device__ __align__(16) float g_WentR[D1 * D2];   // tf32-rounded W_entities
__device__ __align__(16) float g_Y1[(size_t)MPAD * 400];   // [n][ts*200 + h*100 + j]
__device__ __align__(16) float g_Y2[(size_t)MPAD * 400];
__device__ __align__(16) float g_x[NN * D2];       // tf32-rounded (GEMM A for Y2)
__device__ __align__(16) float g_pre[(size_t)MPAD * 208];
__device__ float g_p1[NN * 4];
__device__ float g_p2[NN * 2];
__device__ float g_mask[NN];
__device__ int4  g_edge[ET];
__device__ int   g_rank[ET];
__device__ int   g_cnt[NN];
__device__ int   g_rowptr[NN + 1];
__device__ int   g_csr[ET];
__device__ __align__(16) float g_B1[D1 * 400];     // tf32-rounded
__device__ __align__(16) float g_B2[D2 * 400];     // tf32-rounded
__device__ float g_w1[2 * NR * D1];
__device__ float g_w2[NR * D2];
__device__ float g_q1[2 * NR];
__device__ float g_q2[NR];
__device__ float g_u1[4 * D1];
__device__ float g_u2[2 * D2];
__device__ float g_or1[NR * D2];

__device__ __forceinline__ unsigned sm_u32(const void* p) {
    unsigned r;
    asm("{.reg .u64 t; cvta.to.shared.u64 t, %1; cvt.u32.u64 %0, t;}" : "=r"(r) : "l"(p));
    return r;
}
#define CPA16(dst, src, pred) \
    asm volatile("cp.async.cg.shared.global [%0], [%1], 16, %2;\n" \
                 :: "r"(dst), "l"(src), "r"((pred) ? 16 : 0))

// ---------------- launch 1: init ----------------
__global__ void k_init() {
    int i = blockIdx.x * blockDim.x + threadIdx.x;
    if (i < NN) { g_cnt[i] = 0; g_mask[i] = 0.f; }
}

// ---------------- launch 2: mega1 ----------------
#define M1_BUILD 508
#define M1_MASK  (M1_BUILD + 32)
#define M1_B1    (M1_MASK + 157)
#define M1_B2    (M1_B1 + 313)
#define M1_WENT  (M1_B2 + 79)
#define M1_W1    (M1_WENT + 371)
#define M1_U1    (M1_W1 + 2)
#define M1_U2    (M1_U1 + 2)
#define M1_OR1   (M1_U2 + 371)
#define M1_ORTHO (M1_OR1 + 1)
#define M1_NORM  (M1_ORTHO + 5000)

__global__ void __launch_bounds__(256) k_mega1(
    const int* __restrict__ edge_list, const int* __restrict__ edge_type,
    const int* __restrict__ nhop, const int* __restrict__ batch_inputs,
    const float* __restrict__ emb, const float* __restrict__ rel_emb,
    const float* __restrict__ W_rel, const float* __restrict__ W_ent,
    const float* __restrict__ att_a, const float* __restrict__ att_a2,
    const float* __restrict__ out_a, const float* __restrict__ out_a2,
    float* __restrict__ out) {
    __shared__ float s0[256], s1[256], s2[256];
    int b = blockIdx.x, tid = threadIdx.x;
    if (b < M1_BUILD) {
        int e = b * 256 + tid;
        if (e >= ET) return;
        int t, s, ra, rb;
        if (e < E1) {
            t = edge_list[e]; s = edge_list[E1 + e];
            ra = edge_type[e]; rb = -1;
        } else {
            int i = e - E1;
            t = nhop[i * 4 + 3]; s = nhop[i * 4 + 0];
            ra = nhop[i * 4 + 1]; rb = nhop[i * 4 + 2];
        }
        g_edge[e] = make_int4(t, s, ra, rb);
        g_rank[e] = atomicAdd(&g_cnt[t], 1);
    } else if (b < M1_MASK) {
        int i = (b - M1_BUILD) * 256 + tid;
        if (i < NB) g_mask[batch_inputs[i * 3 + 2]] = 1.0f;
    } else if (b < M1_B1) {
        int i = (b - M1_MASK) * 256 + tid;
        if (i >= D1 * 400) return;
        int k = i / 400, c = i % 400;
        int ts = c / 200, h = (c % 200) / 100, j = c % 100;
        g_B1[i] = wmma::__float_to_tf32(att_a[(h * 100 + j) * 300 + ts * 100 + k]);
    } else if (b < M1_B2) {
        int i = (b - M1_B1) * 256 + tid;
        if (i >= D2 * 400) return;
        int k = i / 400, c = i % 400;
        int ts = c / 200, j = c % 200;
        g_B2[i] = wmma::__float_to_tf32(out_a[j * 600 + ts * 200 + k]);
    } else if (b < M1_WENT) {
        int i = (b - M1_B2) * 256 + tid;
        if (i < D1 * D2) g_WentR[i] = wmma::__float_to_tf32(W_ent[i]);
    } else if (b < M1_W1) {
        int i = (b - M1_WENT) * 256 + tid;
        if (i >= 2 * NR * D1) return;
        int h = i / (NR * D1);
        int rem = i % (NR * D1);
        int r = rem / D1, j = rem % D1;
        float s = 0.f;
#pragma unroll 4
        for (int k = 0; k < D1; k++)
            s += rel_emb[r * D1 + k] * att_a[(h * 100 + j) * 300 + 200 + k];
        g_w1[(h * NR + r) * D1 + j] = s;
    } else if (b < M1_U1) {
        int i = (b - M1_W1) * 256 + tid;
        if (i >= 4 * D1) return;
        int v = i / D1, k = i % D1;
        int h = v / 2, ts = v % 2;
        float s = 0.f;
#pragma unroll 4
        for (int j = 0; j < 100; j++)
            s += att_a[(h * 100 + j) * 300 + ts * 100 + k] * att_a2[h * 100 + j];
        g_u1[i] = s;
    } else if (b < M1_U2) {
        int i = (b - M1_U1) * 256 + tid;
        if (i >= 2 * D2) return;
        int ts = i / D2, k = i % D2;
        float s = 0.f;
#pragma unroll 4
        for (int j = 0; j < 200; j++)
            s += out_a[j * 600 + ts * 200 + k] * out_a2[j];
        g_u2[i] = s;
    } else if (b < M1_OR1) {
        int i = (b - M1_U2) * 256 + tid;
        if (i >= NR * D2) return;
        int r = i / D2, d = i % D2;
        float s = 0.f;
#pragma unroll 4
        for (int k = 0; k < D1; k++) s += rel_emb[r * D1 + k] * W_rel[k * D2 + d];
        g_or1[i] = s;
        out[NN * D2 + i] = s;
    } else if (b < M1_ORTHO) {
        float total = 0.f;
        for (int m = 0; m < 3; m++) {
            const float* base = (m < 2) ? att_a + m * 30000 : out_a;
            int half = (m < 2) ? 15000 : 60000;
            float a00 = 0.f, a01 = 0.f, a11 = 0.f;
            for (int i = tid; i < half; i += 256) {
                float x0 = base[i], x1 = base[half + i];
                a00 += x0 * x0; a01 += x0 * x1; a11 += x1 * x1;
            }
            s0[tid] = a00; s1[tid] = a01; s2[tid] = a11;
            __syncthreads();
            for (int o = 128; o; o >>= 1) {
                if (tid < o) { s0[tid] += s0[tid + o]; s1[tid] += s1[tid + o]; s2[tid] += s2[tid + o]; }
                __syncthreads();
            }
            if (tid == 0) {
                float n0 = fmaxf(sqrtf(s0[0]), EPSV);
                float n1 = fmaxf(sqrtf(s2[0]), EPSV);
                float g00 = s0[0] / (n0 * n0);
                float g11 = s2[0] / (n1 * n1);
                float g01 = s1[0] / (n0 * n1);
                total += 0.01f * ((g00 - 1.f) * (g00 - 1.f) + (g11 - 1.f) * (g11 - 1.f) + 2.f * g01 * g01);
            }
            __syncthreads();
        }
        if (tid == 0) out[NN * D2 + NR * D2] = total;
    } else {
        int n = (b - M1_ORTHO) * 8 + (tid >> 5);
        int lane = tid & 31;
        if (n >= NN) return;
        float v[4]; float ss = 0.f;
#pragma unroll
        for (int j = 0; j < 4; j++) {
            int d = lane + 32 * j;
            v[j] = (d < D1) ? emb[n * D1 + d] : 0.f;
            ss += v[j] * v[j];
        }
#pragma unroll
        for (int o = 16; o; o >>= 1) ss += __shfl_xor_sync(0xffffffffu, ss, o);
        float inv = 1.f / fmaxf(sqrtf(ss), EPSV);
#pragma unroll
        for (int j = 0; j < 4; j++) {
            int d = lane + 32 * j;
            if (d < D1) {
                float val = v[j] * inv;
                g_ent[n * D1 + d] = val;
                g_entR[n * D1 + d] = wmma::__float_to_tf32(val);
            }
        }
    }
}

// ---------------- tf32 wmma GEMM: BM=256 BN=80 BK=32, pre-rounded inputs ----------------
#define ASZ (256 * 40)
#define BSZ (32 * 88)
#define SMEM_GEMM ((2 * ASZ + 2 * BSZ) * 4)

__device__ __forceinline__ void gemm_stage(const float* __restrict__ A, int M, int K,
                                           const float* __restrict__ B, int N,
                                           int bm, int bn, int kk,
                                           unsigned aBase, unsigned bBase, int tid) {
#pragma unroll
    for (int q = 0; q < 8; q++) {
        int idx = q * 256 + tid;
        int m = idx >> 3, kq = (idx & 7) * 4;
        int gm = bm + m, gk = kk + kq;
        bool p = (gm < M) && (gk < K);
        const float* src = p ? &A[(size_t)gm * K + gk] : A;
        CPA16(aBase + (unsigned)(m * 40 + kq) * 4u, src, p);
    }
#pragma unroll
    for (int q = 0; q < 3; q++) {
        int idx = q * 256 + tid;
        if (idx < 640) {
            int k = idx / 20, c4 = (idx % 20) * 4;
            int gk = kk + k, gn = bn + c4;
            bool p = (gk < K) && (gn < N);
            const float* src = p ? &B[(size_t)gk * N + gn] : B;
            CPA16(bBase + (unsigned)(k * 88 + c4) * 4u, src, p);
        }
    }
    asm volatile("cp.async.commit_group;\n" ::);
}

__device__ __forceinline__ void gemm_tf32(const float* __restrict__ A, int M, int K,
                                          const float* __restrict__ B, int N,
                                          float* __restrict__ C, int Npad,
                                          int bx, int by, float* sm) {
    float* As = sm;
    float* Bs = sm + 2 * ASZ;
    const int tid = threadIdx.x;
    const int bm = by * 256, bn = bx * 80;
    const int wm = (tid >> 5) * 32;

    wmma::fragment<wmma::accumulator, 16, 16, 8, float> c[2][5];
#pragma unroll
    for (int i = 0; i < 2; i++)
#pragma unroll
        for (int j = 0; j < 5; j++) wmma::fill_fragment(c[i][j], 0.f);

    const int nk = (K + 31) / 32;
    gemm_stage(A, M, K, B, N, bm, bn, 0, sm_u32(As), sm_u32(Bs), tid);

    int buf = 0;
    for (int kt = 0; kt < nk; kt++) {
        asm volatile("cp.async.wait_group 0;\n" ::);
        __syncthreads();
        if (kt + 1 < nk)
            gemm_stage(A, M, K, B, N, bm, bn, (kt + 1) * 32,
                       sm_u32(As + (buf ^ 1) * ASZ), sm_u32(Bs + (buf ^ 1) * BSZ), tid);
        const float* Ab = As + buf * ASZ;
        const float* Bb = Bs + buf * BSZ;
#pragma unroll
        for (int k8 = 0; k8 < 32; k8 += 8) {
            wmma::fragment<wmma::matrix_a, 16, 16, 8, wmma::precision::tf32, wmma::row_major> a0, a1;
            wmma::load_matrix_sync(a0, &Ab[wm * 40 + k8], 40);
            wmma::load_matrix_sync(a1, &Ab[(wm + 16) * 40 + k8], 40);
#pragma unroll
            for (int j = 0; j < 5; j++) {
                wmma::fragment<wmma::matrix_b, 16, 16, 8, wmma::precision::tf32, wmma::row_major> bf;
                wmma::load_matrix_sync(bf, &Bb[k8 * 88 + j * 16], 88);
                wmma::mma_sync(c[0][j], a0, bf, c[0][j]);
                wmma::mma_sync(c[1][j], a1, bf, c[1][j]);
            }
        }
        buf ^= 1;
    }
#pragma unroll
    for (int i = 0; i < 2; i++) {
        size_t gm = bm + wm + i * 16;
#pragma unroll
        for (int j = 0; j < 5; j++) {
            int gn = bn + j * 16;
            if (gn + 16 <= Npad)
                wmma::store_matrix_sync(&C[gm * Npad + gn], c[i][j], Npad,
                                        wmma::mem_row_major);
        }
    }
}

// ---------------- launch 3: megaA: Y1 GEMM | pre GEMM | scan | w2 | q1 | p1 ----------------
#define A_Y1   785
#define A_PRE  (A_Y1 + 471)
#define A_SCAN (A_PRE + 1)
#define A_W2   (A_SCAN + 371)
#define A_Q1   (A_W2 + 4)
#define A_P1   (A_Q1 + 5000)

__global__ void __launch_bounds__(256) k_megaA(const float* __restrict__ out_a,
                                               const float* __restrict__ att_a2) {
    extern __shared__ float dynsm[];
    __shared__ float su[400];
    __shared__ int ws[8];
    int b = blockIdx.x, t = threadIdx.x;
    if (b < A_Y1) {
        gemm_tf32(g_entR, NN, D1, g_B1, 400, g_Y1, 400, b % 5, b / 5, dynsm);
    } else if (b < A_PRE) {
        int bb = b - A_Y1;
        gemm_tf32(g_entR, NN, D1, g_WentR, D2, g_pre, 208, bb % 3, bb / 3, dynsm);
    } else if (b < A_SCAN) {
        const int PER = 157;
        int base = t * PER;
        int s = 0;
        for (int i = 0; i < PER; i++) {
            int idx = base + i;
            if (idx < NN) s += g_cnt[idx];
        }
        int lane = t & 31, w = t >> 5;
        int v = s;
#pragma unroll
        for (int off = 1; off < 32; off <<= 1) {
            int nv = __shfl_up_sync(0xffffffffu, v, off);
            if (lane >= off) v += nv;
        }
        if (lane == 31) ws[w] = v;
        __syncthreads();
        if (w == 0 && lane < 8) {
            int x = ws[lane];
#pragma unroll
            for (int off = 1; off < 8; off <<= 1) {
                int nv = __shfl_up_sync(0x000000ffu, x, off);
                if (lane >= off) x += nv;
            }
            ws[lane] = x;
        }
        __syncthreads();
        int run = v - s + ((w > 0) ? ws[w - 1] : 0);
        for (int i = 0; i < PER; i++) {
            int idx = base + i;
            if (idx < NN) { g_rowptr[idx] = run; run += g_cnt[idx]; }
        }
        if (t == 255) g_rowptr[NN] = run;
    } else if (b < A_W2) {
        int i = (b - A_SCAN) * 256 + t;
        if (i >= NR * D2) return;
        int r = i / D2, j = i % D2;
        float s = 0.f;
#pragma unroll 4
        for (int k = 0; k < D2; k++)
            s += g_or1[r * D2 + k] * out_a[j * 600 + 400 + k];
        g_w2[i] = s;
    } else if (b < A_Q1) {
        int i = (b - A_W2) * 256 + t;
        if (i >= 2 * NR) return;
        int h = i / NR, r = i % NR;
        float s = 0.f;
#pragma unroll 4
        for (int j = 0; j < D1; j++)
            s += g_w1[(h * NR + r) * D1 + j] * att_a2[h * 100 + j];
        g_q1[i] = s;
    } else {
        for (int i = t; i < 400; i += 256) su[i] = g_u1[i];
        __syncthreads();
        int n = (b - A_Q1) * 8 + (t >> 5);
        int lane = t & 31;
        if (n >= NN) return;
        float e[4];
#pragma unroll
        for (int j = 0; j < 4; j++) {
            int d = lane + 32 * j;
            e[j] = (d < D1) ? g_ent[n * D1 + d] : 0.f;
        }
#pragma unroll
        for (int v = 0; v < 4; v++) {
            float s = 0.f;
#pragma unroll
            for (int j = 0; j < 4; j++) {
                int d = lane + 32 * j;
                if (d < D1) s += e[j] * su[v * D1 + d];
            }
#pragma unroll
            for (int o = 16; o; o >>= 1) s += __shfl_xor_sync(0xffffffffu, s, o);
            if (lane == 0) g_p1[n * 4 + v] = s;
        }
    }
}

// ---------------- launch 4: megaB: atomic-free fill (ILP 4) | q2 ----------------
__global__ void __launch_bounds__(256) k_megaB(const float* __restrict__ out_a2) {
    int b = blockIdx.x, t = threadIdx.x;
    if (b < 127) {
        int base = b * 1024 + t;
#pragma unroll
        for (int q = 0; q < 4; q++) {
            int e = base + q * 256;
            if (e < ET) {
                int tg = g_edge[e].x;
                g_csr[g_rowptr[tg] + g_rank[e]] = e;
            }
        }
    } else {
        int r = (b - 127) * 256 + t;
        if (r >= NR) return;
        float s = 0.f;
#pragma unroll 4
        for (int j = 0; j < D2; j++) s += g_w2[r * D2 + j] * out_a2[j];
        g_q2[r] = s;
    }
}

// ---------------- gather1: ee1 + aggregation + elu + p2 ----------------
__global__ void k_gather1() {
    __shared__ float su2[400];
    for (int i = threadIdx.x; i < 400; i += blockDim.x) su2[i] = g_u2[i];
    __syncthreads();
    int n = (blockIdx.x * blockDim.x + threadIdx.x) >> 5;
    int lane = threadIdx.x & 31;
    if (n >= NN) return;
    int start = g_rowptr[n], end = g_rowptr[n + 1];
    float pt0 = g_p1[n * 4 + 0], pt1 = g_p1[n * 4 + 2];
    float acc[2][4] = {{0.f, 0.f, 0.f, 0.f}, {0.f, 0.f, 0.f, 0.f}};
    float es0 = 0.f, es1 = 0.f;
    for (int i = start; i < end; i++) {
        int e = g_csr[i];
        int4 ed = g_edge[e];
        float sB = (ed.w >= 0) ? 1.f : 0.f;
        int rb = (ed.w >= 0) ? ed.w : ed.z;
        float l0 = pt0 + g_p1[ed.y * 4 + 1] + g_q1[ed.z] + sB * g_q1[rb];
        float l1 = pt1 + g_p1[ed.y * 4 + 3] + g_q1[NR + ed.z] + sB * g_q1[NR + rb];
        float z0 = (l0 >= 0.f) ? l0 : 0.2f * l0;
        float z1 = (l1 >= 0.f) ? l1 : 0.2f * l1;
        float ee0 = expf(-z0), ee1 = expf(-z1);
        const float* ysrc = &g_Y1[(size_t)ed.y * 400 + 200];
#pragma unroll
        for (int j = 0; j < 4; j++) {
            int d = lane + 32 * j;
            if (d < D1) {
                float wa0 = g_w1[ed.z * D1 + d];
                float wb0 = g_w1[rb * D1 + d];
                float wa1 = g_w1[(NR + ed.z) * D1 + d];
                float wb1 = g_w1[(NR + rb) * D1 + d];
                acc[0][j] += ee0 * (ysrc[d] + wa0 + sB * wb0);
                acc[1][j] += ee1 * (ysrc[100 + d] + wa1 + sB * wb1);
            }
        }
        es0 += ee0; es1 += ee1;
    }
    bool has = (end > start);
    float inv0 = has ? 1.f / es0 : 0.f;
    float inv1 = has ? 1.f / es1 : 0.f;
    float pa = 0.f, pb = 0.f;
#pragma unroll
    for (int j = 0; j < 4; j++) {
        int d = lane + 32 * j;
        if (d < D1) {
            float o0 = 0.f, o1 = 0.f;
            if (has) {
                float v0 = g_Y1[(size_t)n * 400 + d] + acc[0][j] * inv0;
                float v1 = g_Y1[(size_t)n * 400 + 100 + d] + acc[1][j] * inv1;
                o0 = (v0 > 0.f) ? v0 : expm1f(v0);
                o1 = (v1 > 0.f) ? v1 : expm1f(v1);
            }
            g_x[(size_t)n * D2 + d] = wmma::__float_to_tf32(o0);
            g_x[(size_t)n * D2 + 100 + d] = wmma::__float_to_tf32(o1);
            pa += o0 * su2[d] + o1 * su2[100 + d];
            pb += o0 * su2[200 + d] + o1 * su2[300 + d];
        }
    }
#pragma unroll
    for (int o = 16; o; o >>= 1) {
        pa += __shfl_xor_sync(0xffffffffu, pa, o);
        pb += __shfl_xor_sync(0xffffffffu, pb, o);
    }
    if (lane == 0) { g_p2[n * 2] = pa; g_p2[n * 2 + 1] = pb; }
}

// ---------------- gemm Y2 ----------------
__global__ void __launch_bounds__(256) k_gemm_Y2() {
    extern __shared__ float dynsm[];
    gemm_tf32(g_x, NN, D2, g_B2, 400, g_Y2, 400, blockIdx.x, blockIdx.y, dynsm);
}

// ---------------- gather2 + final fused ----------------
__global__ void k_gather2final(float* __restrict__ outp) {
    int n = (blockIdx.x * blockDim.x + threadIdx.x) >> 5;
    int lane = threadIdx.x & 31;
    if (n >= NN) return;
    int start = g_rowptr[n], end = g_rowptr[n + 1];
    float pt = g_p2[n * 2];
    float acc[7] = {0.f, 0.f, 0.f, 0.f, 0.f, 0.f, 0.f};
    float es = 0.f;
    for (int i = start; i < end; i++) {
        int e = g_csr[i];
        int4 ed = g_edge[e];
        float sB = (ed.w >= 0) ? 1.f : 0.f;
        int rb = (ed.w >= 0) ? ed.w : ed.z;
        float l = pt + g_p2[ed.y * 2 + 1] + g_q2[ed.z] + sB * g_q2[rb];
        float z = (l >= 0.f) ? l : 0.2f * l;
        float ee = expf(-z);
        const float* ys = &g_Y2[(size_t)ed.y * 400 + 200];
#pragma unroll
        for (int j = 0; j < 7; j++) {
            int d = lane + 32 * j;
            if (d < D2) {
                float v = ys[d] + g_w2[ed.z * D2 + d] + sB * g_w2[rb * D2 + d];
                acc[j] += ee * v;
            }
        }
        es += ee;
    }
    bool has = (end > start);
    float inv = has ? 1.f / es : 0.f;
    float msk = g_mask[n];
    float v[7]; float ss = 0.f;
#pragma unroll
    for (int j = 0; j < 7; j++) {
        int d = lane + 32 * j;
        v[j] = 0.f;
        if (d < D2) {
            float h = has ? (g_Y2[(size_t)n * 400 + d] + acc[j] * inv) : 0.f;
            v[j] = g_pre[(size_t)n * 208 + d] + msk * h;
            ss += v[j] * v[j];
        }
    }
#pragma unroll
    for (int o = 16; o; o >>= 1) ss += __shfl_xor_sync(0xffffffffu, ss, o);
    float inv2 = 1.f / fmaxf(sqrtf(ss), EPSV);
#pragma unroll
    for (int j = 0; j < 7; j++) {
        int d = lane + 32 * j;
        if (d < D2) outp[(size_t)n * D2 + d] = v[j] * inv2;
    }
}

// ---------------- launch ----------------
extern "C" void kernel_launch(void* const* d_in, const int* in_sizes, int n_in,
                              void* d_out, int out_size) {
    const int*   edge_list    = (const int*)d_in[0];
    const int*   edge_type    = (const int*)d_in[1];
    const int*   batch_inputs = (const int*)d_in[2];
    const int*   nhop         = (const int*)d_in[3];
    const float* ent_emb      = (const float*)d_in[4];
    const float* rel_emb      = (const float*)d_in[5];
    const float* W_ent        = (const float*)d_in[6];
    const float* W_rel        = (const float*)d_in[7];
    const float* att_a        = (const float*)d_in[8];
    const float* att_a2       = (const float*)d_in[9];
    const float* out_a        = (const float*)d_in[10];
    const float* out_a2       = (const float*)d_in[11];
    float* out = (float*)d_out;

    cudaFuncSetAttribute(k_megaA, cudaFuncAttributeMaxDynamicSharedMemorySize, SMEM_GEMM);
    cudaFuncSetAttribute(k_gemm_Y2, cudaFuncAttributeMaxDynamicSharedMemorySize, SMEM_GEMM);

    k_init<<<(NN + 255) / 256, 256>>>();
    k_mega1<<<M1_NORM, 256>>>(edge_list, edge_type, nhop, batch_inputs,
                              ent_emb, rel_emb, W_rel, W_ent, att_a, att_a2,
                              out_a, out_a2, out);
    k_megaA<<<A_P1, 256, SMEM_GEMM>>>(out_a, att_a2);
    k_megaB<<<129, 256>>>(out_a2);
    k_gather1<<<NN / 8, 256>>>();
    k_gemm_Y2<<<dim3(5, 157), 256, SMEM_GEMM>>>();
    k_gather2final<<<NN / 8, 256>>>(out);
}

// round 6
// speedup vs baseline: 2.3032x; 1.0218x over previous
#include <cuda_runtime.h>
#include <mma.h>
#include <math.h>
#include <stdint.h>

using namespace nvcuda;

#define NN 40000
#define MPAD 40064
#define NR 474
#define E1 100000
#define ET 130000
#define D1 100
#define D2 200
#define NB 8192
#define EPSV 1e-12f

// ---------------- device scratch ----------------
__device__ __align__(16) float g_ent[NN * D1];
__device__ __align__(16) float g_entR[NN * D1];
__device__ __align__(16) float g_WentR[D1 * D2];
__device__ __align__(16) float g_Y1[(size_t)MPAD * 400];   // [n][ts*200 + h*100 + j]
__device__ __align__(16) float g_Y2[(size_t)MPAD * 400];
__device__ __align__(16) float g_x[NN * D2];
__device__ __align__(16) float g_pre[(size_t)MPAD * 208];
__device__ float g_p1[NN * 4];
__device__ float g_p2[NN * 2];
__device__ float g_mask[NN];
__device__ int4  g_edge[ET];
__device__ int   g_rank[ET];
__device__ int   g_cnt[NN];
__device__ int   g_rowptr[NN + 1];
__device__ int   g_csr[ET];
__device__ __align__(16) float g_B1[D1 * 400];
__device__ __align__(16) float g_B2[D2 * 400];
__device__ float g_w1[2 * NR * D1];
__device__ float g_w2[NR * D2];
__device__ float g_q1[2 * NR];
__device__ float g_q2[NR];
__device__ float g_u1[4 * D1];
__device__ float g_u2[2 * D2];
__device__ float g_or1[NR * D2];
__device__ float g_oacc[9];

__device__ __forceinline__ unsigned sm_u32(const void* p) {
    unsigned r;
    asm("{.reg .u64 t; cvta.to.shared.u64 t, %1; cvt.u32.u64 %0, t;}" : "=r"(r) : "l"(p));
    return r;
}
#define CPA16(dst, src, pred) \
    asm volatile("cp.async.cg.shared.global [%0], [%1], 16, %2;\n" \
                 :: "r"(dst), "l"(src), "r"((pred) ? 16 : 0))

// ---------------- launch 1: init + u1 + u2 ----------------
__global__ void k_init(const float* __restrict__ att_a, const float* __restrict__ att_a2,
                       const float* __restrict__ out_a, const float* __restrict__ out_a2) {
    int b = blockIdx.x, t = threadIdx.x;
    if (b < 157) {
        int i = b * 256 + t;
        if (i < NN) { g_cnt[i] = 0; g_mask[i] = 0.f; }
    } else if (b < 159) {
        int i = (b - 157) * 256 + t;
        if (i >= 4 * D1) return;
        int v = i / D1, k = i % D1;
        int h = v / 2, ts = v % 2;
        float s = 0.f;
#pragma unroll 4
        for (int j = 0; j < 100; j++)
            s += att_a[(h * 100 + j) * 300 + ts * 100 + k] * att_a2[h * 100 + j];
        g_u1[i] = s;
    } else if (b < 161) {
        int i = (b - 159) * 256 + t;
        if (i >= 2 * D2) return;
        int ts = i / D2, k = i % D2;
        float s = 0.f;
#pragma unroll 4
        for (int j = 0; j < 200; j++)
            s += out_a[j * 600 + ts * 200 + k] * out_a2[j];
        g_u2[i] = s;
    } else {
        if (t < 9) g_oacc[t] = 0.f;
    }
}

// ---------------- launch 2: mega1 ----------------
#define M1_BUILD 508
#define M1_MASK  (M1_BUILD + 32)
#define M1_B1    (M1_MASK + 157)
#define M1_B2    (M1_B1 + 313)
#define M1_WENT  (M1_B2 + 79)
#define M1_W1    (M1_WENT + 371)
#define M1_OR1   (M1_W1 + 371)
#define M1_ORTHO (M1_OR1 + 24)
#define M1_NORM  (M1_ORTHO + 5000)

__global__ void __launch_bounds__(256) k_mega1(
    const int* __restrict__ edge_list, const int* __restrict__ edge_type,
    const int* __restrict__ nhop, const int* __restrict__ batch_inputs,
    const float* __restrict__ emb, const float* __restrict__ rel_emb,
    const float* __restrict__ W_rel, const float* __restrict__ W_ent,
    const float* __restrict__ att_a, const float* __restrict__ out_a,
    float* __restrict__ out) {
    __shared__ float s0[256], s1[256], s2[256];
    int b = blockIdx.x, tid = threadIdx.x;
    if (b < M1_BUILD) {
        int e = b * 256 + tid;
        if (e >= ET) return;
        int t, s, ra, rb;
        if (e < E1) {
            t = edge_list[e]; s = edge_list[E1 + e];
            ra = edge_type[e]; rb = -1;
        } else {
            int i = e - E1;
            t = nhop[i * 4 + 3]; s = nhop[i * 4 + 0];
            ra = nhop[i * 4 + 1]; rb = nhop[i * 4 + 2];
        }
        g_edge[e] = make_int4(t, s, ra, rb);
        g_rank[e] = atomicAdd(&g_cnt[t], 1);
    } else if (b < M1_MASK) {
        int i = (b - M1_BUILD) * 256 + tid;
        if (i < NB) g_mask[batch_inputs[i * 3 + 2]] = 1.0f;
    } else if (b < M1_B1) {
        int i = (b - M1_MASK) * 256 + tid;
        if (i >= D1 * 400) return;
        int k = i / 400, c = i % 400;
        int ts = c / 200, h = (c % 200) / 100, j = c % 100;
        g_B1[i] = wmma::__float_to_tf32(att_a[(h * 100 + j) * 300 + ts * 100 + k]);
    } else if (b < M1_B2) {
        int i = (b - M1_B1) * 256 + tid;
        if (i >= D2 * 400) return;
        int k = i / 400, c = i % 400;
        int ts = c / 200, j = c % 200;
        g_B2[i] = wmma::__float_to_tf32(out_a[j * 600 + ts * 200 + k]);
    } else if (b < M1_WENT) {
        int i = (b - M1_B2) * 256 + tid;
        if (i < D1 * D2) g_WentR[i] = wmma::__float_to_tf32(W_ent[i]);
    } else if (b < M1_W1) {
        int i = (b - M1_WENT) * 256 + tid;
        if (i >= 2 * NR * D1) return;
        int h = i / (NR * D1);
        int rem = i % (NR * D1);
        int r = rem / D1, j = rem % D1;
        float s = 0.f;
#pragma unroll 4
        for (int k = 0; k < D1; k++)
            s += rel_emb[r * D1 + k] * att_a[(h * 100 + j) * 300 + 200 + k];
        g_w1[(h * NR + r) * D1 + j] = s;
    } else if (b < M1_OR1) {
        int i = (b - M1_W1) * 256 + tid;
        if (i >= NR * D2) return;
        int r = i / D2, d = i % D2;
        float s = 0.f;
#pragma unroll 4
        for (int k = 0; k < D1; k++) s += rel_emb[r * D1 + k] * W_rel[k * D2 + d];
        g_or1[i] = s;
        out[NN * D2 + i] = s;
    } else if (b < M1_ORTHO) {
        int ob = b - M1_OR1;
        int m = ob >> 3, c = ob & 7;
        const float* base = (m < 2) ? att_a + m * 30000 : out_a;
        int half = (m < 2) ? 15000 : 60000;
        int len = (half + 7) / 8;
        int lo = c * len, hi = min(lo + len, half);
        float a00 = 0.f, a01 = 0.f, a11 = 0.f;
        for (int i = lo + tid; i < hi; i += 256) {
            float x0 = base[i], x1 = base[half + i];
            a00 += x0 * x0; a01 += x0 * x1; a11 += x1 * x1;
        }
        s0[tid] = a00; s1[tid] = a01; s2[tid] = a11;
        __syncthreads();
        for (int o = 128; o; o >>= 1) {
            if (tid < o) { s0[tid] += s0[tid + o]; s1[tid] += s1[tid + o]; s2[tid] += s2[tid + o]; }
            __syncthreads();
        }
        if (tid == 0) {
            atomicAdd(&g_oacc[m * 3 + 0], s0[0]);
            atomicAdd(&g_oacc[m * 3 + 1], s1[0]);
            atomicAdd(&g_oacc[m * 3 + 2], s2[0]);
        }
    } else {
        // norm + entR + p1 fused
        int n = (b - M1_ORTHO) * 8 + (tid >> 5);
        int lane = tid & 31;
        if (n >= NN) return;
        float v[4]; float ss = 0.f;
#pragma unroll
        for (int j = 0; j < 4; j++) {
            int d = lane + 32 * j;
            v[j] = (d < D1) ? emb[n * D1 + d] : 0.f;
            ss += v[j] * v[j];
        }
#pragma unroll
        for (int o = 16; o; o >>= 1) ss += __shfl_xor_sync(0xffffffffu, ss, o);
        float inv = 1.f / fmaxf(sqrtf(ss), EPSV);
#pragma unroll
        for (int j = 0; j < 4; j++) v[j] *= inv;
#pragma unroll
        for (int j = 0; j < 4; j++) {
            int d = lane + 32 * j;
            if (d < D1) {
                g_ent[n * D1 + d] = v[j];
                g_entR[n * D1 + d] = wmma::__float_to_tf32(v[j]);
            }
        }
#pragma unroll
        for (int p = 0; p < 4; p++) {
            float s = 0.f;
#pragma unroll
            for (int j = 0; j < 4; j++) {
                int d = lane + 32 * j;
                if (d < D1) s += v[j] * __ldg(&g_u1[p * D1 + d]);
            }
#pragma unroll
            for (int o = 16; o; o >>= 1) s += __shfl_xor_sync(0xffffffffu, s, o);
            if (lane == 0) g_p1[n * 4 + p] = s;
        }
    }
}

// ---------------- tf32 wmma GEMM: BM=128 BN=80 BK=32, 3 blocks/SM ----------------
#define ASZ (128 * 40)
#define BSZ (32 * 88)
#define SMEM_GEMM ((2 * ASZ + 2 * BSZ) * 4)

__device__ __forceinline__ void gemm_stage(const float* __restrict__ A, int M, int K,
                                           const float* __restrict__ B, int N,
                                           int bm, int bn, int kk,
                                           unsigned aBase, unsigned bBase, int tid) {
#pragma unroll
    for (int q = 0; q < 4; q++) {
        int idx = q * 256 + tid;
        int m = idx >> 3, kq = (idx & 7) * 4;
        int gm = bm + m, gk = kk + kq;
        bool p = (gm < M) && (gk < K);
        const float* src = p ? &A[(size_t)gm * K + gk] : A;
        CPA16(aBase + (unsigned)(m * 40 + kq) * 4u, src, p);
    }
#pragma unroll
    for (int q = 0; q < 3; q++) {
        int idx = q * 256 + tid;
        if (idx < 640) {
            int k = idx / 20, c4 = (idx % 20) * 4;
            int gk = kk + k, gn = bn + c4;
            bool p = (gk < K) && (gn < N);
            const float* src = p ? &B[(size_t)gk * N + gn] : B;
            CPA16(bBase + (unsigned)(k * 88 + c4) * 4u, src, p);
        }
    }
    asm volatile("cp.async.commit_group;\n" ::);
}

__device__ __forceinline__ void gemm_tf32(const float* __restrict__ A, int M, int K,
                                          const float* __restrict__ B, int N,
                                          float* __restrict__ C, int Npad,
                                          int bx, int by, float* sm) {
    float* As = sm;
    float* Bs = sm + 2 * ASZ;
    const int tid = threadIdx.x;
    const int bm = by * 128, bn = bx * 80;
    const int wm = (tid >> 5) * 16;

    wmma::fragment<wmma::accumulator, 16, 16, 8, float> c[5];
#pragma unroll
    for (int j = 0; j < 5; j++) wmma::fill_fragment(c[j], 0.f);

    const int nk = (K + 31) / 32;
    gemm_stage(A, M, K, B, N, bm, bn, 0, sm_u32(As), sm_u32(Bs), tid);

    int buf = 0;
    for (int kt = 0; kt < nk; kt++) {
        asm volatile("cp.async.wait_group 0;\n" ::);
        __syncthreads();
        if (kt + 1 < nk)
            gemm_stage(A, M, K, B, N, bm, bn, (kt + 1) * 32,
                       sm_u32(As + (buf ^ 1) * ASZ), sm_u32(Bs + (buf ^ 1) * BSZ), tid);
        const float* Ab = As + buf * ASZ;
        const float* Bb = Bs + buf * BSZ;
#pragma unroll
        for (int k8 = 0; k8 < 32; k8 += 8) {
            wmma::fragment<wmma::matrix_a, 16, 16, 8, wmma::precision::tf32, wmma::row_major> a;
            wmma::load_matrix_sync(a, &Ab[wm * 40 + k8], 40);
#pragma unroll
            for (int j = 0; j < 5; j++) {
                wmma::fragment<wmma::matrix_b, 16, 16, 8, wmma::precision::tf32, wmma::row_major> bf;
                wmma::load_matrix_sync(bf, &Bb[k8 * 88 + j * 16], 88);
                wmma::mma_sync(c[j], a, bf, c[j]);
            }
        }
        buf ^= 1;
    }
#pragma unroll
    for (int j = 0; j < 5; j++) {
        int gn = bn + j * 16;
        if (gn + 16 <= Npad)
            wmma::store_matrix_sync(&C[(size_t)(bm + wm) * Npad + gn], c[j], Npad,
                                    wmma::mem_row_major);
    }
}

// ---------------- launch 3: megaA: scan | w2 | q1 | ortho-final ----------------
#define A_W2  372
#define A_Q1  376
#define A_ORT 377

__global__ void __launch_bounds__(256) k_megaA(const float* __restrict__ out_a,
                                               const float* __restrict__ att_a2,
                                               float* __restrict__ out) {
    __shared__ int ws[8];
    int b = blockIdx.x, t = threadIdx.x;
    if (b == 0) {
        const int PER = 157;
        int base = t * PER;
        int s = 0;
        for (int i = 0; i < PER; i++) {
            int idx = base + i;
            if (idx < NN) s += g_cnt[idx];
        }
        int lane = t & 31, w = t >> 5;
        int v = s;
#pragma unroll
        for (int off = 1; off < 32; off <<= 1) {
            int nv = __shfl_up_sync(0xffffffffu, v, off);
            if (lane >= off) v += nv;
        }
        if (lane == 31) ws[w] = v;
        __syncthreads();
        if (w == 0 && lane < 8) {
            int x = ws[lane];
#pragma unroll
            for (int off = 1; off < 8; off <<= 1) {
                int nv = __shfl_up_sync(0x000000ffu, x, off);
                if (lane >= off) x += nv;
            }
            ws[lane] = x;
        }
        __syncthreads();
        int run = v - s + ((w > 0) ? ws[w - 1] : 0);
        for (int i = 0; i < PER; i++) {
            int idx = base + i;
            if (idx < NN) { g_rowptr[idx] = run; run += g_cnt[idx]; }
        }
        if (t == 255) g_rowptr[NN] = run;
    } else if (b < A_W2) {
        int i = (b - 1) * 256 + t;
        if (i >= NR * D2) return;
        int r = i / D2, j = i % D2;
        float s = 0.f;
#pragma unroll 4
        for (int k = 0; k < D2; k++)
            s += g_or1[r * D2 + k] * out_a[j * 600 + 400 + k];
        g_w2[i] = s;
    } else if (b < A_Q1) {
        int i = (b - A_W2) * 256 + t;
        if (i >= 2 * NR) return;
        int h = i / NR, r = i % NR;
        float s = 0.f;
#pragma unroll 4
        for (int j = 0; j < D1; j++)
            s += g_w1[(h * NR + r) * D1 + j] * att_a2[h * 100 + j];
        g_q1[i] = s;
    } else {
        if (t == 0) {
            float total = 0.f;
#pragma unroll
            for (int m = 0; m < 3; m++) {
                float a00 = g_oacc[m * 3 + 0], a01 = g_oacc[m * 3 + 1], a11 = g_oacc[m * 3 + 2];
                float n0 = fmaxf(sqrtf(a00), EPSV);
                float n1 = fmaxf(sqrtf(a11), EPSV);
                float g00 = a00 / (n0 * n0);
                float g11 = a11 / (n1 * n1);
                float g01 = a01 / (n0 * n1);
                total += 0.01f * ((g00 - 1.f) * (g00 - 1.f) + (g11 - 1.f) * (g11 - 1.f) + 2.f * g01 * g01);
            }
            out[NN * D2 + NR * D2] = total;
        }
    }
}

// ---------------- launch 4: megaB: Y1 GEMM | pre GEMM | fill | q2 ----------------
#define B_Y1   1565
#define B_PRE  (B_Y1 + 939)
#define B_FILL (B_PRE + 508)
#define B_Q2   (B_FILL + 2)

__global__ void __launch_bounds__(256, 3) k_megaB(const float* __restrict__ out_a2) {
    extern __shared__ float dynsm[];
    int b = blockIdx.x, t = threadIdx.x;
    if (b < B_Y1) {
        gemm_tf32(g_entR, NN, D1, g_B1, 400, g_Y1, 400, b % 5, b / 5, dynsm);
    } else if (b < B_PRE) {
        int bb = b - B_Y1;
        gemm_tf32(g_entR, NN, D1, g_WentR, D2, g_pre, 208, bb % 3, bb / 3, dynsm);
    } else if (b < B_FILL) {
        int e = (b - B_PRE) * 256 + t;
        if (e >= ET) return;
        int tg = g_edge[e].x;
        g_csr[g_rowptr[tg] + g_rank[e]] = e;
    } else {
        int r = (b - B_FILL) * 256 + t;
        if (r >= NR) return;
        float s = 0.f;
#pragma unroll 4
        for (int j = 0; j < D2; j++) s += g_w2[r * D2 + j] * out_a2[j];
        g_q2[r] = s;
    }
}

// ---------------- gather1: ee1 + aggregation + elu + p2 ----------------
__global__ void k_gather1() {
    __shared__ float su2[400];
    for (int i = threadIdx.x; i < 400; i += blockDim.x) su2[i] = g_u2[i];
    __syncthreads();
    int n = (blockIdx.x * blockDim.x + threadIdx.x) >> 5;
    int lane = threadIdx.x & 31;
    if (n >= NN) return;
    int start = g_rowptr[n], end = g_rowptr[n + 1];
    float pt0 = g_p1[n * 4 + 0], pt1 = g_p1[n * 4 + 2];
    float acc[2][4] = {{0.f, 0.f, 0.f, 0.f}, {0.f, 0.f, 0.f, 0.f}};
    float es0 = 0.f, es1 = 0.f;
    for (int i = start; i < end; i++) {
        int e = g_csr[i];
        int4 ed = g_edge[e];
        float sB = (ed.w >= 0) ? 1.f : 0.f;
        int rb = (ed.w >= 0) ? ed.w : ed.z;
        float l0 = pt0 + g_p1[ed.y * 4 + 1] + g_q1[ed.z] + sB * g_q1[rb];
        float l1 = pt1 + g_p1[ed.y * 4 + 3] + g_q1[NR + ed.z] + sB * g_q1[NR + rb];
        float z0 = (l0 >= 0.f) ? l0 : 0.2f * l0;
        float z1 = (l1 >= 0.f) ? l1 : 0.2f * l1;
        float ee0 = expf(-z0), ee1 = expf(-z1);
        const float* ysrc = &g_Y1[(size_t)ed.y * 400 + 200];
#pragma unroll
        for (int j = 0; j < 4; j++) {
            int d = lane + 32 * j;
            if (d < D1) {
                float wa0 = g_w1[ed.z * D1 + d];
                float wb0 = g_w1[rb * D1 + d];
                float wa1 = g_w1[(NR + ed.z) * D1 + d];
                float wb1 = g_w1[(NR + rb) * D1 + d];
                acc[0][j] += ee0 * (ysrc[d] + wa0 + sB * wb0);
                acc[1][j] += ee1 * (ysrc[100 + d] + wa1 + sB * wb1);
            }
        }
        es0 += ee0; es1 += ee1;
    }
    bool has = (end > start);
    float inv0 = has ? 1.f / es0 : 0.f;
    float inv1 = has ? 1.f / es1 : 0.f;
    float pa = 0.f, pb = 0.f;
#pragma unroll
    for (int j = 0; j < 4; j++) {
        int d = lane + 32 * j;
        if (d < D1) {
            float o0 = 0.f, o1 = 0.f;
            if (has) {
                float v0 = g_Y1[(size_t)n * 400 + d] + acc[0][j] * inv0;
                float v1 = g_Y1[(size_t)n * 400 + 100 + d] + acc[1][j] * inv1;
                o0 = (v0 > 0.f) ? v0 : expm1f(v0);
                o1 = (v1 > 0.f) ? v1 : expm1f(v1);
            }
            g_x[(size_t)n * D2 + d] = wmma::__float_to_tf32(o0);
            g_x[(size_t)n * D2 + 100 + d] = wmma::__float_to_tf32(o1);
            pa += o0 * su2[d] + o1 * su2[100 + d];
            pb += o0 * su2[200 + d] + o1 * su2[300 + d];
        }
    }
#pragma unroll
    for (int o = 16; o; o >>= 1) {
        pa += __shfl_xor_sync(0xffffffffu, pa, o);
        pb += __shfl_xor_sync(0xffffffffu, pb, o);
    }
    if (lane == 0) { g_p2[n * 2] = pa; g_p2[n * 2 + 1] = pb; }
}

// ---------------- gemm Y2 ----------------
__global__ void __launch_bounds__(256, 3) k_gemm_Y2() {
    extern __shared__ float dynsm[];
    gemm_tf32(g_x, NN, D2, g_B2, 400, g_Y2, 400, blockIdx.x, blockIdx.y, dynsm);
}

// ---------------- gather2 + final fused ----------------
__global__ void k_gather2final(float* __restrict__ outp) {
    int n = (blockIdx.x * blockDim.x + threadIdx.x) >> 5;
    int lane = threadIdx.x & 31;
    if (n >= NN) return;
    int start = g_rowptr[n], end = g_rowptr[n + 1];
    float pt = g_p2[n * 2];
    float acc[7] = {0.f, 0.f, 0.f, 0.f, 0.f, 0.f, 0.f};
    float es = 0.f;
    for (int i = start; i < end; i++) {
        int e = g_csr[i];
        int4 ed = g_edge[e];
        float sB = (ed.w >= 0) ? 1.f : 0.f;
        int rb = (ed.w >= 0) ? ed.w : ed.z;
        float l = pt + g_p2[ed.y * 2 + 1] + g_q2[ed.z] + sB * g_q2[rb];
        float z = (l >= 0.f) ? l : 0.2f * l;
        float ee = expf(-z);
        const float* ys = &g_Y2[(size_t)ed.y * 400 + 200];
#pragma unroll
        for (int j = 0; j < 7; j++) {
            int d = lane + 32 * j;
            if (d < D2) {
                float v = ys[d] + g_w2[ed.z * D2 + d] + sB * g_w2[rb * D2 + d];
                acc[j] += ee * v;
            }
        }
        es += ee;
    }
    bool has = (end > start);
    float inv = has ? 1.f / es : 0.f;
    float msk = g_mask[n];
    float v[7]; float ss = 0.f;
#pragma unroll
    for (int j = 0; j < 7; j++) {
        int d = lane + 32 * j;
        v[j] = 0.f;
        if (d < D2) {
            float h = has ? (g_Y2[(size_t)n * 400 + d] + acc[j] * inv) : 0.f;
            v[j] = g_pre[(size_t)n * 208 + d] + msk * h;
            ss += v[j] * v[j];
        }
    }
#pragma unroll
    for (int o = 16; o; o >>= 1) ss += __shfl_xor_sync(0xffffffffu, ss, o);
    float inv2 = 1.f / fmaxf(sqrtf(ss), EPSV);
#pragma unroll
    for (int j = 0; j < 7; j++) {
        int d = lane + 32 * j;
        if (d < D2) outp[(size_t)n * D2 + d] = v[j] * inv2;
    }
}

// ---------------- launch ----------------
extern "C" void kernel_launch(void* const* d_in, const int* in_sizes, int n_in,
                              void* d_out, int out_size) {
    const int*   edge_list    = (const int*)d_in[0];
    const int*   edge_type    = (const int*)d_in[1];
    const int*   batch_inputs = (const int*)d_in[2];
    const int*   nhop         = (const int*)d_in[3];
    const float* ent_emb      = (const float*)d_in[4];
    const float* rel_emb      = (const float*)d_in[5];
    const float* W_ent        = (const float*)d_in[6];
    const float* W_rel        = (const float*)d_in[7];
    const float* att_a        = (const float*)d_in[8];
    const float* att_a2       = (const float*)d_in[9];
    const float* out_a        = (const float*)d_in[10];
    const float* out_a2       = (const float*)d_in[11];
    float* out = (float*)d_out;

    cudaFuncSetAttribute(k_megaB, cudaFuncAttributeMaxDynamicSharedMemorySize, SMEM_GEMM);
    cudaFuncSetAttribute(k_gemm_Y2, cudaFuncAttributeMaxDynamicSharedMemorySize, SMEM_GEMM);

    k_init<<<162, 256>>>(att_a, att_a2, out_a, out_a2);
    k_mega1<<<M1_NORM, 256>>>(edge_list, edge_type, nhop, batch_inputs,
                              ent_emb, rel_emb, W_rel, W_ent, att_a, out_a, out);
    k_megaA<<<A_ORT + 1, 256>>>(out_a, att_a2, out);
    k_megaB<<<B_Q2, 256, SMEM_GEMM>>>(out_a2);
    k_gather1<<<NN / 8, 256>>>();
    k_gemm_Y2<<<dim3(5, 313), 256, SMEM_GEMM>>>();
    k_gather2final<<<NN / 8, 256>>>(out);
}